// round 2
// baseline (speedup 1.0000x reference)
#include <cuda_runtime.h>
#include <cuda_bf16.h>
#include <math.h>

#define N_USER 100000
#define N_ITEM 100000
#define NNODE  200000
#define E_HALF 600000
#define E_TOT  1200000
#define HID 128

// ------------------------- scratch (device globals, no alloc) ----------------
__device__ float g_h[(size_t)NNODE * HID];    // node features (current layer input)
__device__ float g_hw[(size_t)NNODE * HID];   // h @ W before aggregation
__device__ float g_dinv[NNODE];
__device__ int   g_deg[NNODE];
__device__ int   g_rowptr[NNODE + 1];
__device__ int   g_cursor[NNODE];
__device__ int   g_col[E_TOT];
__device__ int   g_bsums[256];

// ------------------------- CSR build ----------------------------------------
__global__ void zero_deg() {
    int i = blockIdx.x * blockDim.x + threadIdx.x;
    if (i < NNODE) g_deg[i] = 0;
}

__global__ void build_deg(const int* __restrict__ eui, const int* __restrict__ eiu) {
    int i = blockIdx.x * blockDim.x + threadIdx.x;
    if (i < E_HALF) {
        int d = eui[E_HALF + i] + N_USER;           // user->item : dst is item
        atomicAdd(&g_deg[d], 1);
    } else if (i < E_TOT) {
        int j = i - E_HALF;
        int d = eiu[E_HALF + j];                     // item->user : dst is user
        atomicAdd(&g_deg[d], 1);
    }
}

__global__ void compute_dinv() {
    int i = blockIdx.x * blockDim.x + threadIdx.x;
    if (i < NNODE) g_dinv[i] = rsqrtf((float)(g_deg[i] + 1));  // +1 self loop
}

// block-wise inclusive scan (1024/block), writes exclusive values + block sums
__global__ void scan1() {
    __shared__ int sm[1024];
    int tx = threadIdx.x;
    int i = blockIdx.x * 1024 + tx;
    int v = (i < NNODE) ? g_deg[i] : 0;
    sm[tx] = v;
    __syncthreads();
    #pragma unroll
    for (int off = 1; off < 1024; off <<= 1) {
        int t = (tx >= off) ? sm[tx - off] : 0;
        __syncthreads();
        sm[tx] += t;
        __syncthreads();
    }
    if (i < NNODE) g_rowptr[i] = sm[tx] - v;         // exclusive within block
    if (tx == 1023) g_bsums[blockIdx.x] = sm[1023];
}

__global__ void scan2(int nb) {   // exclusive scan of block sums (tiny)
    if (threadIdx.x == 0 && blockIdx.x == 0) {
        int run = 0;
        for (int b = 0; b < nb; b++) { int v = g_bsums[b]; g_bsums[b] = run; run += v; }
    }
}

__global__ void scan3() {
    int tx = threadIdx.x;
    int i = blockIdx.x * 1024 + tx;
    if (i < NNODE) {
        int v = g_rowptr[i] + g_bsums[blockIdx.x];
        g_rowptr[i] = v;
        g_cursor[i] = v;
    }
    if (i == 0) g_rowptr[NNODE] = E_TOT;
}

__global__ void fill_csr(const int* __restrict__ eui, const int* __restrict__ eiu) {
    int i = blockIdx.x * blockDim.x + threadIdx.x;
    int s, d;
    if (i < E_HALF) {
        s = eui[i];
        d = eui[E_HALF + i] + N_USER;
    } else if (i < E_TOT) {
        int j = i - E_HALF;
        s = eiu[j] + N_USER;
        d = eiu[E_HALF + j];
    } else return;
    int pos = atomicAdd(&g_cursor[d], 1);
    g_col[pos] = s;
}

// ------------------------- fp32 GEMM: C[M,128] = A[M,K] @ B[K,128] (+bias) ---
// BM=64, BN=128, BK=16, 256 threads, each thread 4x8 outputs.
template <bool ADD_BIAS>
__global__ __launch_bounds__(256)
void sgemm_n128(const float* __restrict__ A, const float* __restrict__ B,
                const float* __restrict__ bias, float* __restrict__ C,
                int M, int K) {
    __shared__ float As[64][16];
    __shared__ float Bs[16][128];

    const int tid = threadIdx.x;
    const int tm = tid >> 4;         // 0..15 -> rows tm*4..tm*4+3
    const int tn = tid & 15;         // 0..15 -> cols tn*8..tn*8+7
    const int block_row = blockIdx.x * 64;

    float acc[4][8];
    #pragma unroll
    for (int i = 0; i < 4; i++)
        #pragma unroll
        for (int j = 0; j < 8; j++) acc[i][j] = 0.f;

    for (int k0 = 0; k0 < K; k0 += 16) {
        // A tile: 64x16 = 256 float4
        {
            int r = tid >> 2, c = (tid & 3) << 2;
            int grow = block_row + r;
            float4 v = make_float4(0.f, 0.f, 0.f, 0.f);
            if (grow < M) v = *(const float4*)(A + (size_t)grow * K + k0 + c);
            *(float4*)&As[r][c] = v;
        }
        // B tile: 16x128 = 512 float4 -> 2 per thread
        {
            int i0 = tid;
            int r = i0 >> 5, c = (i0 & 31) << 2;
            *(float4*)&Bs[r][c] = *(const float4*)(B + (size_t)(k0 + r) * 128 + c);
            int i1 = tid + 256;
            r = i1 >> 5; c = (i1 & 31) << 2;
            *(float4*)&Bs[r][c] = *(const float4*)(B + (size_t)(k0 + r) * 128 + c);
        }
        __syncthreads();

        #pragma unroll
        for (int k = 0; k < 16; k++) {
            float a[4];
            #pragma unroll
            for (int i = 0; i < 4; i++) a[i] = As[tm * 4 + i][k];
            float b[8];
            *(float4*)&b[0] = *(float4*)&Bs[k][tn * 8];
            *(float4*)&b[4] = *(float4*)&Bs[k][tn * 8 + 4];
            #pragma unroll
            for (int i = 0; i < 4; i++)
                #pragma unroll
                for (int j = 0; j < 8; j++)
                    acc[i][j] = fmaf(a[i], b[j], acc[i][j]);
        }
        __syncthreads();
    }

    float bv[8];
    if (ADD_BIAS) {
        *(float4*)&bv[0] = *(const float4*)(bias + tn * 8);
        *(float4*)&bv[4] = *(const float4*)(bias + tn * 8 + 4);
    }
    #pragma unroll
    for (int i = 0; i < 4; i++) {
        int grow = block_row + tm * 4 + i;
        if (grow < M) {
            float4 o0, o1;
            o0.x = acc[i][0]; o0.y = acc[i][1]; o0.z = acc[i][2]; o0.w = acc[i][3];
            o1.x = acc[i][4]; o1.y = acc[i][5]; o1.z = acc[i][6]; o1.w = acc[i][7];
            if (ADD_BIAS) {
                o0.x += bv[0]; o0.y += bv[1]; o0.z += bv[2]; o0.w += bv[3];
                o1.x += bv[4]; o1.y += bv[5]; o1.z += bv[6]; o1.w += bv[7];
            }
            float* cp = C + (size_t)grow * 128 + tn * 8;
            *(float4*)cp = o0;
            *(float4*)(cp + 4) = o1;
        }
    }
}

// ------------------------- aggregation: one warp per dst node ----------------
// out[d] = relu?( sum_{s in N(d)} hw[s]*dinv[s]*dinv[d] + hw[d]*dinv[d]^2 + bias )
__global__ __launch_bounds__(256)
void aggregate(const float* __restrict__ hw, float* __restrict__ out,
               const float* __restrict__ bias, int relu) {
    int node = (blockIdx.x * blockDim.x + threadIdx.x) >> 5;
    int lane = threadIdx.x & 31;
    if (node >= NNODE) return;

    float dv = g_dinv[node];
    float ws = dv * dv;
    float4 acc = ((const float4*)(hw + (size_t)node * HID))[lane];
    acc.x *= ws; acc.y *= ws; acc.z *= ws; acc.w *= ws;

    int e = g_rowptr[node];
    int end = g_rowptr[node + 1];
    for (; e + 1 < end; e += 2) {
        int s0 = g_col[e], s1 = g_col[e + 1];
        float w0 = g_dinv[s0] * dv;
        float w1 = g_dinv[s1] * dv;
        float4 u0 = ((const float4*)(hw + (size_t)s0 * HID))[lane];
        float4 u1 = ((const float4*)(hw + (size_t)s1 * HID))[lane];
        acc.x = fmaf(w0, u0.x, acc.x); acc.y = fmaf(w0, u0.y, acc.y);
        acc.z = fmaf(w0, u0.z, acc.z); acc.w = fmaf(w0, u0.w, acc.w);
        acc.x = fmaf(w1, u1.x, acc.x); acc.y = fmaf(w1, u1.y, acc.y);
        acc.z = fmaf(w1, u1.z, acc.z); acc.w = fmaf(w1, u1.w, acc.w);
    }
    if (e < end) {
        int s0 = g_col[e];
        float w0 = g_dinv[s0] * dv;
        float4 u0 = ((const float4*)(hw + (size_t)s0 * HID))[lane];
        acc.x = fmaf(w0, u0.x, acc.x); acc.y = fmaf(w0, u0.y, acc.y);
        acc.z = fmaf(w0, u0.z, acc.z); acc.w = fmaf(w0, u0.w, acc.w);
    }

    float4 b = ((const float4*)bias)[lane];
    acc.x += b.x; acc.y += b.y; acc.z += b.z; acc.w += b.w;
    if (relu) {
        acc.x = fmaxf(acc.x, 0.f); acc.y = fmaxf(acc.y, 0.f);
        acc.z = fmaxf(acc.z, 0.f); acc.w = fmaxf(acc.w, 0.f);
    }
    ((float4*)(out + (size_t)node * HID))[lane] = acc;
}

// ------------------------- driver -------------------------------------------
extern "C" void kernel_launch(void* const* d_in, const int* in_sizes, int n_in,
                              void* d_out, int out_size) {
    const float* x_user    = (const float*)d_in[0];
    const float* x_item    = (const float*)d_in[1];
    const int*   edge_ui   = (const int*)d_in[2];
    const int*   edge_iu   = (const int*)d_in[3];
    const float* W_in_user = (const float*)d_in[4];
    const float* b_in_user = (const float*)d_in[5];
    const float* W_in_item = (const float*)d_in[6];
    const float* b_in_item = (const float*)d_in[7];
    const float* W1        = (const float*)d_in[8];
    const float* b1        = (const float*)d_in[9];
    const float* W2        = (const float*)d_in[10];
    const float* b2        = (const float*)d_in[11];
    float* out = (float*)d_out;

    float* h;  float* hw;
    cudaGetSymbolAddress((void**)&h,  g_h);
    cudaGetSymbolAddress((void**)&hw, g_hw);

    const int NB_SCAN = (NNODE + 1023) / 1024;  // 196

    // CSR build
    zero_deg<<<(NNODE + 255) / 256, 256>>>();
    build_deg<<<(E_TOT + 255) / 256, 256>>>(edge_ui, edge_iu);
    compute_dinv<<<(NNODE + 255) / 256, 256>>>();
    scan1<<<NB_SCAN, 1024>>>();
    scan2<<<1, 32>>>(NB_SCAN);
    scan3<<<NB_SCAN, 1024>>>();
    fill_csr<<<(E_TOT + 255) / 256, 256>>>(edge_ui, edge_iu);

    // input projection (with bias), writes g_h
    sgemm_n128<true><<<(N_USER + 63) / 64, 256>>>(x_user, W_in_user, b_in_user,
                                                  h, N_USER, 256);
    sgemm_n128<true><<<(N_ITEM + 63) / 64, 256>>>(x_item, W_in_item, b_in_item,
                                                  h + (size_t)N_USER * HID, N_ITEM, 256);

    // layer 1: hw = h @ W1 ; h = relu(agg(hw) + b1)
    sgemm_n128<false><<<(NNODE + 63) / 64, 256>>>(h, W1, nullptr, hw, NNODE, 128);
    aggregate<<<(NNODE * 32 + 255) / 256, 256>>>(hw, h, b1, 1);

    // layer 2: hw = h @ W2 ; out = agg(hw) + b2
    sgemm_n128<false><<<(NNODE + 63) / 64, 256>>>(h, W2, nullptr, hw, NNODE, 128);
    aggregate<<<(NNODE * 32 + 255) / 256, 256>>>(hw, out, b2, 0);
}

// round 4
// speedup vs baseline: 1.8842x; 1.8842x over previous
#include <cuda_runtime.h>
#include <cuda_bf16.h>
#include <math.h>
#include <stdint.h>

#define N_USER 100000
#define N_ITEM 100000
#define NNODE  200000
#define E_HALF 600000
#define E_TOT  1200000
#define HID 128

// ------------------------- scratch (device globals, no alloc) ----------------
__device__ float g_h[(size_t)NNODE * HID];
__device__ float g_hw[(size_t)NNODE * HID];
__device__ float g_dinv[NNODE];
__device__ int   g_deg[NNODE];
__device__ int   g_rowptr[NNODE + 1];
__device__ int   g_cursor[NNODE];
__device__ int   g_col[E_TOT];
__device__ int   g_bsums[256];

// bf16 hi/lo planes of the four weight matrices, stored as Wt[n][k] (n=0..127)
// offsets (in halves): W_in_user 0 (128x256), W_in_item 32768 (128x256),
//                      W1 65536 (128x128), W2 81920 (128x128)
#define WT_WU 0
#define WT_WI 32768
#define WT_W1 65536
#define WT_W2 81920
__device__ __nv_bfloat16 g_wt_hi[98304];
__device__ __nv_bfloat16 g_wt_lo[98304];

// ------------------------- helpers -------------------------------------------
__device__ __forceinline__ uint32_t smem_u32(const void* p) {
    uint32_t a;
    asm("{ .reg .u64 t; cvta.to.shared.u64 t, %1; cvt.u32.u64 %0, t; }" : "=r"(a) : "l"(p));
    return a;
}

__device__ __forceinline__ void ldsm_x4(uint32_t& r0, uint32_t& r1,
                                        uint32_t& r2, uint32_t& r3, uint32_t addr) {
    asm volatile("ldmatrix.sync.aligned.m8n8.x4.shared.b16 {%0,%1,%2,%3}, [%4];"
                 : "=r"(r0), "=r"(r1), "=r"(r2), "=r"(r3) : "r"(addr));
}

__device__ __forceinline__ void mma16816(float* c, const uint32_t* a, const uint32_t* b) {
    asm volatile("mma.sync.aligned.m16n8k16.row.col.f32.bf16.bf16.f32 "
                 "{%0,%1,%2,%3}, {%4,%5,%6,%7}, {%8,%9}, {%0,%1,%2,%3};"
                 : "+f"(c[0]), "+f"(c[1]), "+f"(c[2]), "+f"(c[3])
                 : "r"(a[0]), "r"(a[1]), "r"(a[2]), "r"(a[3]), "r"(b[0]), "r"(b[1]));
}

__device__ __forceinline__ uint32_t pack2(__nv_bfloat16 a, __nv_bfloat16 b) {
    return (uint32_t)__bfloat16_as_ushort(a) | ((uint32_t)__bfloat16_as_ushort(b) << 16);
}

// ------------------------- CSR build ------------------------------------------
__global__ void zero_deg() {
    int i = blockIdx.x * blockDim.x + threadIdx.x;
    if (i < NNODE) g_deg[i] = 0;
}

__global__ void build_deg(const int* __restrict__ eui, const int* __restrict__ eiu) {
    int i = blockIdx.x * blockDim.x + threadIdx.x;
    if (i < E_HALF) {
        atomicAdd(&g_deg[eui[E_HALF + i] + N_USER], 1);
    } else if (i < E_TOT) {
        atomicAdd(&g_deg[eiu[E_HALF + (i - E_HALF)]], 1);
    }
}

__global__ void compute_dinv() {
    int i = blockIdx.x * blockDim.x + threadIdx.x;
    if (i < NNODE) g_dinv[i] = rsqrtf((float)(g_deg[i] + 1));
}

__global__ void scan1() {
    __shared__ int sm[1024];
    int tx = threadIdx.x;
    int i = blockIdx.x * 1024 + tx;
    int v = (i < NNODE) ? g_deg[i] : 0;
    sm[tx] = v;
    __syncthreads();
    #pragma unroll
    for (int off = 1; off < 1024; off <<= 1) {
        int t = (tx >= off) ? sm[tx - off] : 0;
        __syncthreads();
        sm[tx] += t;
        __syncthreads();
    }
    if (i < NNODE) g_rowptr[i] = sm[tx] - v;
    if (tx == 1023) g_bsums[blockIdx.x] = sm[1023];
}

__global__ void scan2(int nb) {
    if (threadIdx.x == 0 && blockIdx.x == 0) {
        int run = 0;
        for (int b = 0; b < nb; b++) { int v = g_bsums[b]; g_bsums[b] = run; run += v; }
    }
}

__global__ void scan3() {
    int tx = threadIdx.x;
    int i = blockIdx.x * 1024 + tx;
    if (i < NNODE) {
        int v = g_rowptr[i] + g_bsums[blockIdx.x];
        g_rowptr[i] = v;
        g_cursor[i] = v;
    }
    if (i == 0) g_rowptr[NNODE] = E_TOT;
}

__global__ void fill_csr(const int* __restrict__ eui, const int* __restrict__ eiu) {
    int i = blockIdx.x * blockDim.x + threadIdx.x;
    int s, d;
    if (i < E_HALF) {
        s = eui[i];
        d = eui[E_HALF + i] + N_USER;
    } else if (i < E_TOT) {
        int j = i - E_HALF;
        s = eiu[j] + N_USER;
        d = eiu[E_HALF + j];
    } else return;
    int pos = atomicAdd(&g_cursor[d], 1);
    g_col[pos] = s;
}

// ------------------------- weight conversion (once per call) ------------------
// W[k][n] fp32 -> Wt[n][k] bf16 hi/lo planes in device globals.
__global__ void convert_weights(const float* __restrict__ Wu, const float* __restrict__ Wi,
                                const float* __restrict__ W1, const float* __restrict__ W2) {
    int i = blockIdx.x * blockDim.x + threadIdx.x;
    if (i >= 98304) return;
    float w;
    int dst;
    if (i < 32768) {                    // Wu: K=256
        int n = i & 127, k = i >> 7;
        w = Wu[(size_t)k * 128 + n];
        dst = WT_WU + n * 256 + k;
    } else if (i < 65536) {             // Wi: K=256
        int j = i - 32768;
        int n = j & 127, k = j >> 7;
        w = Wi[(size_t)k * 128 + n];
        dst = WT_WI + n * 256 + k;
    } else if (i < 81920) {             // W1: K=128
        int j = i - 65536;
        int n = j & 127, k = j >> 7;
        w = W1[(size_t)k * 128 + n];
        dst = WT_W1 + n * 128 + k;
    } else {                            // W2: K=128
        int j = i - 81920;
        int n = j & 127, k = j >> 7;
        w = W2[(size_t)k * 128 + n];
        dst = WT_W2 + n * 128 + k;
    }
    __nv_bfloat16 hi = __float2bfloat16_rn(w);
    __nv_bfloat16 lo = __float2bfloat16_rn(w - __bfloat162float(hi));
    g_wt_hi[dst] = hi;
    g_wt_lo[dst] = lo;
}

// ------------------------- HMMA GEMM: C[M,128] = A[M,K] @ W[K,128] ------------
// split-bf16 (hi/lo), 3 products, fp32 accum via mma.sync.m16n8k16.
// CTA: 128x128, 8 warps in 2(M)x4(N), warp tile 64x32, K step 16, A double-buffered.
template <int K, bool BIAS>
__global__ __launch_bounds__(256) void gemm_mma(
    const float* __restrict__ A, const __nv_bfloat16* __restrict__ Wt_hi,
    const __nv_bfloat16* __restrict__ Wt_lo, const float* __restrict__ bias,
    float* __restrict__ C, int M)
{
    constexpr int WSTRIDE = (K + 8) * 2;   // bytes per W smem row (16B-aligned, conflict-free)
    constexpr int WBYTES  = 128 * WSTRIDE;
    constexpr int ASTRIDE = 48;            // bytes per A smem row (16 halves + 8 pad)
    constexpr int ABYTES  = 128 * ASTRIDE; // 6144
    constexpr int NCH     = K / 16;

    extern __shared__ char smem[];
    char* sWhi = smem;
    char* sWlo = smem + WBYTES;
    char* sA   = smem + 2 * WBYTES;        // 4 buffers: [db][hi/lo]

    const int tid = threadIdx.x, lane = tid & 31, wid = tid >> 5;
    const int m0 = (wid >> 2) * 64, n0 = (wid & 3) * 32;
    const int block_row = blockIdx.x * 128;

    const uint32_t sWhi_u = smem_u32(sWhi);
    const uint32_t sWlo_u = smem_u32(sWlo);
    const uint32_t sA_u   = smem_u32(sA);

    // ---- stage W (bf16, already split) into padded smem ----
    {
        const uint32_t* wh = (const uint32_t*)Wt_hi;
        const uint32_t* wl = (const uint32_t*)Wt_lo;
        #pragma unroll 4
        for (int i = tid; i < 128 * (K / 2); i += 256) {
            int n = i / (K / 2), kp = i % (K / 2);
            *(uint32_t*)(sWhi + n * WSTRIDE + kp * 4) = wh[i];
            *(uint32_t*)(sWlo + n * WSTRIDE + kp * 4) = wl[i];
        }
    }

    float acc[4][4][4];
    #pragma unroll
    for (int a = 0; a < 4; a++)
        #pragma unroll
        for (int b = 0; b < 4; b++)
            #pragma unroll
            for (int c = 0; c < 4; c++) acc[a][b][c] = 0.f;

    // per-thread ldmatrix offsets
    const uint32_t aoff = (uint32_t)((lane & 15) * ASTRIDE + ((lane & 16) ? 16 : 0));
    const uint32_t woff = (uint32_t)((((lane & 16) ? 8 : 0) + (lane & 7)) * WSTRIDE +
                                     ((lane & 8) ? 16 : 0));

    // A tile staging: thread q∈{0,1} handles float4 j = tid + 256q: row j>>2, part j&3
    float4 va[2];
    const int r0 = tid >> 2, p0 = tid & 3;
    const int r1 = (tid + 256) >> 2, p1 = tid & 3;

    auto load_tile = [&](int ck) {
        int row0 = block_row + r0, row1 = block_row + r1;
        va[0] = (row0 < M) ? *(const float4*)(A + (size_t)row0 * K + ck * 16 + p0 * 4)
                           : make_float4(0.f, 0.f, 0.f, 0.f);
        va[1] = (row1 < M) ? *(const float4*)(A + (size_t)row1 * K + ck * 16 + p1 * 4)
                           : make_float4(0.f, 0.f, 0.f, 0.f);
    };
    auto store_tile = [&](int db) {
        char* bhi = sA + (db * 2 + 0) * ABYTES;
        char* blo = sA + (db * 2 + 1) * ABYTES;
        #pragma unroll
        for (int q = 0; q < 2; q++) {
            int r = q ? r1 : r0;
            int p = q ? p1 : p0;
            float v[4] = {va[q].x, va[q].y, va[q].z, va[q].w};
            #pragma unroll
            for (int e = 0; e < 4; e += 2) {
                __nv_bfloat16 h0 = __float2bfloat16_rn(v[e]);
                __nv_bfloat16 h1 = __float2bfloat16_rn(v[e + 1]);
                __nv_bfloat16 l0 = __float2bfloat16_rn(v[e] - __bfloat162float(h0));
                __nv_bfloat16 l1 = __float2bfloat16_rn(v[e + 1] - __bfloat162float(h1));
                int off = r * ASTRIDE + (p * 4 + e) * 2;
                *(uint32_t*)(bhi + off) = pack2(h0, h1);
                *(uint32_t*)(blo + off) = pack2(l0, l1);
            }
        }
    };

    // prologue
    load_tile(0);
    store_tile(0);
    __syncthreads();

    for (int ck = 0; ck < NCH; ck++) {
        if (ck + 1 < NCH) load_tile(ck + 1);

        // compute on buffer ck&1
        const uint32_t abase_hi = sA_u + ((ck & 1) * 2 + 0) * ABYTES;
        const uint32_t abase_lo = abase_hi + ABYTES;
        const uint32_t wk = (uint32_t)(n0 * WSTRIDE + ck * 32) + woff;   // k0*2 = ck*32

        #pragma unroll
        for (int pr = 0; pr < 3; pr++) {
            const uint32_t ab = (pr == 1) ? abase_lo : abase_hi;
            const uint32_t wb = ((pr == 2) ? sWlo_u : sWhi_u) + wk;
            uint32_t bfr[4][2];
            #pragma unroll
            for (int nt2 = 0; nt2 < 2; nt2++) {
                uint32_t q0, q1, q2, q3;
                ldsm_x4(q0, q1, q2, q3, wb + nt2 * 16 * WSTRIDE);
                bfr[nt2 * 2 + 0][0] = q0; bfr[nt2 * 2 + 0][1] = q1;
                bfr[nt2 * 2 + 1][0] = q2; bfr[nt2 * 2 + 1][1] = q3;
            }
            #pragma unroll
            for (int mt = 0; mt < 4; mt++) {
                uint32_t af[4];
                ldsm_x4(af[0], af[1], af[2], af[3],
                        ab + (uint32_t)((m0 + mt * 16) * ASTRIDE) + aoff);
                #pragma unroll
                for (int nt = 0; nt < 4; nt++)
                    mma16816(acc[mt][nt], af, bfr[nt]);
            }
        }
        __syncthreads();
        if (ck + 1 < NCH) {
            store_tile((ck + 1) & 1);
            __syncthreads();
        }
    }

    // ---- epilogue ----
    #pragma unroll
    for (int nt = 0; nt < 4; nt++) {
        int col = n0 + nt * 8 + 2 * (lane & 3);
        float b0 = 0.f, b1 = 0.f;
        if (BIAS) { b0 = bias[col]; b1 = bias[col + 1]; }
        #pragma unroll
        for (int mt = 0; mt < 4; mt++) {
            int row = block_row + m0 + mt * 16 + (lane >> 2);
            if (row < M) {
                float2 o = make_float2(acc[mt][nt][0] + b0, acc[mt][nt][1] + b1);
                *(float2*)(C + (size_t)row * 128 + col) = o;
            }
            if (row + 8 < M) {
                float2 o = make_float2(acc[mt][nt][2] + b0, acc[mt][nt][3] + b1);
                *(float2*)(C + (size_t)(row + 8) * 128 + col) = o;
            }
        }
    }
}

// ------------------------- aggregation: one warp per dst node ----------------
__global__ __launch_bounds__(256)
void aggregate(const float* __restrict__ hw, float* __restrict__ out,
               const float* __restrict__ bias, int relu) {
    int node = (blockIdx.x * blockDim.x + threadIdx.x) >> 5;
    int lane = threadIdx.x & 31;
    if (node >= NNODE) return;

    float dv = g_dinv[node];
    float ws = dv * dv;
    float4 acc = ((const float4*)(hw + (size_t)node * HID))[lane];
    acc.x *= ws; acc.y *= ws; acc.z *= ws; acc.w *= ws;

    int e = g_rowptr[node];
    int end = g_rowptr[node + 1];
    for (; e + 1 < end; e += 2) {
        int s0 = g_col[e], s1 = g_col[e + 1];
        float w0 = g_dinv[s0] * dv;
        float w1 = g_dinv[s1] * dv;
        float4 u0 = ((const float4*)(hw + (size_t)s0 * HID))[lane];
        float4 u1 = ((const float4*)(hw + (size_t)s1 * HID))[lane];
        acc.x = fmaf(w0, u0.x, acc.x); acc.y = fmaf(w0, u0.y, acc.y);
        acc.z = fmaf(w0, u0.z, acc.z); acc.w = fmaf(w0, u0.w, acc.w);
        acc.x = fmaf(w1, u1.x, acc.x); acc.y = fmaf(w1, u1.y, acc.y);
        acc.z = fmaf(w1, u1.z, acc.z); acc.w = fmaf(w1, u1.w, acc.w);
    }
    if (e < end) {
        int s0 = g_col[e];
        float w0 = g_dinv[s0] * dv;
        float4 u0 = ((const float4*)(hw + (size_t)s0 * HID))[lane];
        acc.x = fmaf(w0, u0.x, acc.x); acc.y = fmaf(w0, u0.y, acc.y);
        acc.z = fmaf(w0, u0.z, acc.z); acc.w = fmaf(w0, u0.w, acc.w);
    }

    float4 b = ((const float4*)bias)[lane];
    acc.x += b.x; acc.y += b.y; acc.z += b.z; acc.w += b.w;
    if (relu) {
        acc.x = fmaxf(acc.x, 0.f); acc.y = fmaxf(acc.y, 0.f);
        acc.z = fmaxf(acc.z, 0.f); acc.w = fmaxf(acc.w, 0.f);
    }
    ((float4*)(out + (size_t)node * HID))[lane] = acc;
}

// ------------------------- driver --------------------------------------------
extern "C" void kernel_launch(void* const* d_in, const int* in_sizes, int n_in,
                              void* d_out, int out_size) {
    const float* x_user    = (const float*)d_in[0];
    const float* x_item    = (const float*)d_in[1];
    const int*   edge_ui   = (const int*)d_in[2];
    const int*   edge_iu   = (const int*)d_in[3];
    const float* W_in_user = (const float*)d_in[4];
    const float* b_in_user = (const float*)d_in[5];
    const float* W_in_item = (const float*)d_in[6];
    const float* b_in_item = (const float*)d_in[7];
    const float* W1        = (const float*)d_in[8];
    const float* b1        = (const float*)d_in[9];
    const float* W2        = (const float*)d_in[10];
    const float* b2        = (const float*)d_in[11];
    float* out = (float*)d_out;

    float* h;  float* hw;
    __nv_bfloat16* wt_hi; __nv_bfloat16* wt_lo;
    cudaGetSymbolAddress((void**)&h,  g_h);
    cudaGetSymbolAddress((void**)&hw, g_hw);
    cudaGetSymbolAddress((void**)&wt_hi, g_wt_hi);
    cudaGetSymbolAddress((void**)&wt_lo, g_wt_lo);

    // dynamic smem: 2 * 128*(K+8)*2 (W planes) + 4 * 6144 (A buffers)
    const int SMEM_K256 = 2 * 128 * (256 + 8) * 2 + 4 * 6144;  // 159744
    const int SMEM_K128 = 2 * 128 * (128 + 8) * 2 + 4 * 6144;  // 94208
    cudaFuncSetAttribute(gemm_mma<256, true>,
                         cudaFuncAttributeMaxDynamicSharedMemorySize, SMEM_K256);
    cudaFuncSetAttribute(gemm_mma<128, false>,
                         cudaFuncAttributeMaxDynamicSharedMemorySize, SMEM_K128);

    const int NB_SCAN = (NNODE + 1023) / 1024;  // 196

    // CSR build + weight conversion
    zero_deg<<<(NNODE + 255) / 256, 256>>>();
    build_deg<<<(E_TOT + 255) / 256, 256>>>(edge_ui, edge_iu);
    compute_dinv<<<(NNODE + 255) / 256, 256>>>();
    scan1<<<NB_SCAN, 1024>>>();
    scan2<<<1, 32>>>(NB_SCAN);
    scan3<<<NB_SCAN, 1024>>>();
    fill_csr<<<(E_TOT + 255) / 256, 256>>>(edge_ui, edge_iu);
    convert_weights<<<(98304 + 255) / 256, 256>>>(W_in_user, W_in_item, W1, W2);

    // input projection
    gemm_mma<256, true><<<(N_USER + 127) / 128, 256, SMEM_K256>>>(
        x_user, wt_hi + WT_WU, wt_lo + WT_WU, b_in_user, h, N_USER);
    gemm_mma<256, true><<<(N_ITEM + 127) / 128, 256, SMEM_K256>>>(
        x_item, wt_hi + WT_WI, wt_lo + WT_WI, b_in_item, h + (size_t)N_USER * HID, N_ITEM);

    // layer 1
    gemm_mma<128, false><<<(NNODE + 127) / 128, 256, SMEM_K128>>>(
        h, wt_hi + WT_W1, wt_lo + WT_W1, nullptr, hw, NNODE);
    aggregate<<<(NNODE * 32 + 255) / 256, 256>>>(hw, h, b1, 1);

    // layer 2
    gemm_mma<128, false><<<(NNODE + 127) / 128, 256, SMEM_K128>>>(
        h, wt_hi + WT_W2, wt_lo + WT_W2, nullptr, hw, NNODE);
    aggregate<<<(NNODE * 32 + 255) / 256, 256>>>(hw, out, b2, 0);
}

// round 5
// speedup vs baseline: 2.2333x; 1.1853x over previous
#include <cuda_runtime.h>
#include <cuda_bf16.h>
#include <cuda_fp16.h>
#include <math.h>
#include <stdint.h>

#define N_USER 100000
#define N_ITEM 100000
#define NNODE  200000
#define E_HALF 600000
#define E_TOT  1200000
#define HID 128

// ------------------------- scratch (device globals, no alloc) ----------------
__device__ float  g_h[(size_t)NNODE * HID];      // fp32 activations (agg1 output)
__device__ __half g_hw16[(size_t)NNODE * HID];   // fp16 pre-aggregation features
__device__ float  g_dinv[NNODE];
__device__ int    g_deg[NNODE];
__device__ int    g_rowptr[NNODE + 1];
__device__ int    g_cursor[NNODE];
__device__ int    g_col[E_TOT];
__device__ int    g_bsums[256];
__device__ float  g_bfold[2][HID];               // b_in @ W1 per node type

// bf16 hi/lo planes, transposed Wt[n][k]:
//   folded user (128x256) at 0, folded item (128x256) at 32768, W2 (128x128) at 65536
#define WT_WU 0
#define WT_WI 32768
#define WT_W2 65536
__device__ __nv_bfloat16 g_wt_hi[81920];
__device__ __nv_bfloat16 g_wt_lo[81920];

// ------------------------- helpers -------------------------------------------
__device__ __forceinline__ uint32_t smem_u32(const void* p) {
    uint32_t a;
    asm("{ .reg .u64 t; cvta.to.shared.u64 t, %1; cvt.u32.u64 %0, t; }" : "=r"(a) : "l"(p));
    return a;
}

__device__ __forceinline__ void ldsm_x4(uint32_t& r0, uint32_t& r1,
                                        uint32_t& r2, uint32_t& r3, uint32_t addr) {
    asm volatile("ldmatrix.sync.aligned.m8n8.x4.shared.b16 {%0,%1,%2,%3}, [%4];"
                 : "=r"(r0), "=r"(r1), "=r"(r2), "=r"(r3) : "r"(addr));
}

__device__ __forceinline__ void mma16816(float* c, const uint32_t* a, const uint32_t* b) {
    asm volatile("mma.sync.aligned.m16n8k16.row.col.f32.bf16.bf16.f32 "
                 "{%0,%1,%2,%3}, {%4,%5,%6,%7}, {%8,%9}, {%0,%1,%2,%3};"
                 : "+f"(c[0]), "+f"(c[1]), "+f"(c[2]), "+f"(c[3])
                 : "r"(a[0]), "r"(a[1]), "r"(a[2]), "r"(a[3]), "r"(b[0]), "r"(b[1]));
}

__device__ __forceinline__ uint32_t pack2(__nv_bfloat16 a, __nv_bfloat16 b) {
    return (uint32_t)__bfloat16_as_ushort(a) | ((uint32_t)__bfloat16_as_ushort(b) << 16);
}

// ------------------------- CSR build ------------------------------------------
__global__ void zero_deg() {
    int i = blockIdx.x * blockDim.x + threadIdx.x;
    if (i < NNODE) g_deg[i] = 0;
}

__global__ void build_deg(const int* __restrict__ eui, const int* __restrict__ eiu) {
    int i = blockIdx.x * blockDim.x + threadIdx.x;
    if (i < E_HALF) {
        atomicAdd(&g_deg[eui[E_HALF + i] + N_USER], 1);
    } else if (i < E_TOT) {
        atomicAdd(&g_deg[eiu[E_HALF + (i - E_HALF)]], 1);
    }
}

__global__ void scan1() {
    __shared__ int sm[1024];
    int tx = threadIdx.x;
    int i = blockIdx.x * 1024 + tx;
    int v = (i < NNODE) ? g_deg[i] : 0;
    sm[tx] = v;
    __syncthreads();
    #pragma unroll
    for (int off = 1; off < 1024; off <<= 1) {
        int t = (tx >= off) ? sm[tx - off] : 0;
        __syncthreads();
        sm[tx] += t;
        __syncthreads();
    }
    if (i < NNODE) g_rowptr[i] = sm[tx] - v;
    if (tx == 1023) g_bsums[blockIdx.x] = sm[1023];
}

__global__ void scan2(int nb) {
    if (threadIdx.x == 0 && blockIdx.x == 0) {
        int run = 0;
        for (int b = 0; b < nb; b++) { int v = g_bsums[b]; g_bsums[b] = run; run += v; }
    }
}

__global__ void scan3() {   // also computes dinv
    int tx = threadIdx.x;
    int i = blockIdx.x * 1024 + tx;
    if (i < NNODE) {
        int v = g_rowptr[i] + g_bsums[blockIdx.x];
        g_rowptr[i] = v;
        g_cursor[i] = v;
        g_dinv[i] = rsqrtf((float)(g_deg[i] + 1));
    }
    if (i == 0) g_rowptr[NNODE] = E_TOT;
}

__global__ void fill_csr(const int* __restrict__ eui, const int* __restrict__ eiu) {
    int i = blockIdx.x * blockDim.x + threadIdx.x;
    int s, d;
    if (i < E_HALF) {
        s = eui[i];
        d = eui[E_HALF + i] + N_USER;
    } else if (i < E_TOT) {
        int j = i - E_HALF;
        s = eiu[j] + N_USER;
        d = eiu[E_HALF + j];
    } else return;
    int pos = atomicAdd(&g_cursor[d], 1);
    g_col[pos] = s;
}

// ------------------------- weight prep ----------------------------------------
// Wfold[k][n] = sum_j W_in[k][j] * W1[j][n]  -> store transposed hi/lo at [n][k]
__global__ void fold_weights(const float* __restrict__ Wu, const float* __restrict__ Wi,
                             const float* __restrict__ W1) {
    int i = blockIdx.x * blockDim.x + threadIdx.x;   // 2*256*128
    if (i >= 2 * 256 * 128) return;
    int type = i >> 15;                // 0=user, 1=item
    int k = (i >> 7) & 255;
    int n = i & 127;
    const float* Win = type ? Wi : Wu;
    float s = 0.f;
    #pragma unroll 8
    for (int j = 0; j < 128; j++)
        s = fmaf(Win[(size_t)k * 128 + j], W1[(size_t)j * 128 + n], s);
    __nv_bfloat16 hi = __float2bfloat16_rn(s);
    __nv_bfloat16 lo = __float2bfloat16_rn(s - __bfloat162float(hi));
    int dst = (type ? WT_WI : WT_WU) + n * 256 + k;
    g_wt_hi[dst] = hi;
    g_wt_lo[dst] = lo;
}

__global__ void fold_bias(const float* __restrict__ bu, const float* __restrict__ bi,
                          const float* __restrict__ W1) {
    int n = threadIdx.x;               // 128 threads
    float su = 0.f, si = 0.f;
    for (int j = 0; j < 128; j++) {
        float w = W1[(size_t)j * 128 + n];
        su = fmaf(bu[j], w, su);
        si = fmaf(bi[j], w, si);
    }
    g_bfold[0][n] = su;
    g_bfold[1][n] = si;
}

__global__ void conv_w2(const float* __restrict__ W2) {
    int i = blockIdx.x * blockDim.x + threadIdx.x;   // 128*128
    if (i >= 128 * 128) return;
    int k = i >> 7, n = i & 127;
    float w = W2[(size_t)k * 128 + n];
    __nv_bfloat16 hi = __float2bfloat16_rn(w);
    __nv_bfloat16 lo = __float2bfloat16_rn(w - __bfloat162float(hi));
    int dst = WT_W2 + n * 128 + k;
    g_wt_hi[dst] = hi;
    g_wt_lo[dst] = lo;
}

// ------------------------- HMMA GEMM: C[M,128] = A[M,K] @ W[K,128] ------------
// split-bf16 (hi/lo), 3 products, fp32 accum, fp16 output.
template <int K, bool BIAS>
__global__ __launch_bounds__(256) void gemm_mma(
    const float* __restrict__ A, const __nv_bfloat16* __restrict__ Wt_hi,
    const __nv_bfloat16* __restrict__ Wt_lo, const float* __restrict__ bias,
    __half* __restrict__ C, int M)
{
    constexpr int WSTRIDE = (K + 8) * 2;
    constexpr int WBYTES  = 128 * WSTRIDE;
    constexpr int ASTRIDE = 48;
    constexpr int ABYTES  = 128 * ASTRIDE;
    constexpr int NCH     = K / 16;

    extern __shared__ char smem[];
    char* sWhi = smem;
    char* sWlo = smem + WBYTES;
    char* sA   = smem + 2 * WBYTES;

    const int tid = threadIdx.x, lane = tid & 31, wid = tid >> 5;
    const int m0 = (wid >> 2) * 64, n0 = (wid & 3) * 32;
    const int block_row = blockIdx.x * 128;

    const uint32_t sWhi_u = smem_u32(sWhi);
    const uint32_t sWlo_u = smem_u32(sWlo);
    const uint32_t sA_u   = smem_u32(sA);

    {
        const uint32_t* wh = (const uint32_t*)Wt_hi;
        const uint32_t* wl = (const uint32_t*)Wt_lo;
        #pragma unroll 4
        for (int i = tid; i < 128 * (K / 2); i += 256) {
            int n = i / (K / 2), kp = i % (K / 2);
            *(uint32_t*)(sWhi + n * WSTRIDE + kp * 4) = wh[i];
            *(uint32_t*)(sWlo + n * WSTRIDE + kp * 4) = wl[i];
        }
    }

    float acc[4][4][4];
    #pragma unroll
    for (int a = 0; a < 4; a++)
        #pragma unroll
        for (int b = 0; b < 4; b++)
            #pragma unroll
            for (int c = 0; c < 4; c++) acc[a][b][c] = 0.f;

    const uint32_t aoff = (uint32_t)((lane & 15) * ASTRIDE + ((lane & 16) ? 16 : 0));
    const uint32_t woff = (uint32_t)((((lane & 16) ? 8 : 0) + (lane & 7)) * WSTRIDE +
                                     ((lane & 8) ? 16 : 0));

    float4 va[2];
    const int r0 = tid >> 2, p0 = tid & 3;
    const int r1 = (tid + 256) >> 2, p1 = tid & 3;

    auto load_tile = [&](int ck) {
        int row0 = block_row + r0, row1 = block_row + r1;
        va[0] = (row0 < M) ? *(const float4*)(A + (size_t)row0 * K + ck * 16 + p0 * 4)
                           : make_float4(0.f, 0.f, 0.f, 0.f);
        va[1] = (row1 < M) ? *(const float4*)(A + (size_t)row1 * K + ck * 16 + p1 * 4)
                           : make_float4(0.f, 0.f, 0.f, 0.f);
    };
    auto store_tile = [&](int db) {
        char* bhi = sA + (db * 2 + 0) * ABYTES;
        char* blo = sA + (db * 2 + 1) * ABYTES;
        #pragma unroll
        for (int q = 0; q < 2; q++) {
            int r = q ? r1 : r0;
            int p = q ? p1 : p0;
            float v[4] = {va[q].x, va[q].y, va[q].z, va[q].w};
            #pragma unroll
            for (int e = 0; e < 4; e += 2) {
                __nv_bfloat16 h0 = __float2bfloat16_rn(v[e]);
                __nv_bfloat16 h1 = __float2bfloat16_rn(v[e + 1]);
                __nv_bfloat16 l0 = __float2bfloat16_rn(v[e] - __bfloat162float(h0));
                __nv_bfloat16 l1 = __float2bfloat16_rn(v[e + 1] - __bfloat162float(h1));
                int off = r * ASTRIDE + (p * 4 + e) * 2;
                *(uint32_t*)(bhi + off) = pack2(h0, h1);
                *(uint32_t*)(blo + off) = pack2(l0, l1);
            }
        }
    };

    load_tile(0);
    store_tile(0);
    __syncthreads();

    for (int ck = 0; ck < NCH; ck++) {
        if (ck + 1 < NCH) load_tile(ck + 1);

        const uint32_t abase_hi = sA_u + ((ck & 1) * 2 + 0) * ABYTES;
        const uint32_t abase_lo = abase_hi + ABYTES;
        const uint32_t wk = (uint32_t)(n0 * WSTRIDE + ck * 32) + woff;

        #pragma unroll
        for (int pr = 0; pr < 3; pr++) {
            const uint32_t ab = (pr == 1) ? abase_lo : abase_hi;
            const uint32_t wb = ((pr == 2) ? sWlo_u : sWhi_u) + wk;
            uint32_t bfr[4][2];
            #pragma unroll
            for (int nt2 = 0; nt2 < 2; nt2++) {
                uint32_t q0, q1, q2, q3;
                ldsm_x4(q0, q1, q2, q3, wb + nt2 * 16 * WSTRIDE);
                bfr[nt2 * 2 + 0][0] = q0; bfr[nt2 * 2 + 0][1] = q1;
                bfr[nt2 * 2 + 1][0] = q2; bfr[nt2 * 2 + 1][1] = q3;
            }
            #pragma unroll
            for (int mt = 0; mt < 4; mt++) {
                uint32_t af[4];
                ldsm_x4(af[0], af[1], af[2], af[3],
                        ab + (uint32_t)((m0 + mt * 16) * ASTRIDE) + aoff);
                #pragma unroll
                for (int nt = 0; nt < 4; nt++)
                    mma16816(acc[mt][nt], af, bfr[nt]);
            }
        }
        __syncthreads();
        if (ck + 1 < NCH) {
            store_tile((ck + 1) & 1);
            __syncthreads();
        }
    }

    // ---- epilogue: fp16 output ----
    #pragma unroll
    for (int nt = 0; nt < 4; nt++) {
        int col = n0 + nt * 8 + 2 * (lane & 3);
        float b0 = 0.f, b1 = 0.f;
        if (BIAS) { b0 = bias[col]; b1 = bias[col + 1]; }
        #pragma unroll
        for (int mt = 0; mt < 4; mt++) {
            int row = block_row + m0 + mt * 16 + (lane >> 2);
            if (row < M) {
                *(__half2*)(C + (size_t)row * 128 + col) =
                    __floats2half2_rn(acc[mt][nt][0] + b0, acc[mt][nt][1] + b1);
            }
            if (row + 8 < M) {
                *(__half2*)(C + (size_t)(row + 8) * 128 + col) =
                    __floats2half2_rn(acc[mt][nt][2] + b0, acc[mt][nt][3] + b1);
            }
        }
    }
}

// ------------------------- aggregation: one warp per dst node ----------------
// reads fp16 hw rows (256B), writes fp32. lane covers cols [4*lane, 4*lane+4)
__global__ __launch_bounds__(256)
void aggregate(const __half* __restrict__ hw, float* __restrict__ out,
               const float* __restrict__ bias, int relu) {
    int node = (blockIdx.x * blockDim.x + threadIdx.x) >> 5;
    int lane = threadIdx.x & 31;
    if (node >= NNODE) return;

    float dv = g_dinv[node];
    float ws = dv * dv;

    const __half2* self = (const __half2*)(hw + (size_t)node * HID) + lane * 2;
    float2 s0 = __half22float2(self[0]);
    float2 s1 = __half22float2(self[1]);
    float4 acc = make_float4(s0.x * ws, s0.y * ws, s1.x * ws, s1.y * ws);

    int e = g_rowptr[node];
    int end = g_rowptr[node + 1];
    for (; e + 1 < end; e += 2) {
        int c0 = g_col[e], c1 = g_col[e + 1];
        float w0 = g_dinv[c0] * dv;
        float w1 = g_dinv[c1] * dv;
        const __half2* u0 = (const __half2*)(hw + (size_t)c0 * HID) + lane * 2;
        const __half2* u1 = (const __half2*)(hw + (size_t)c1 * HID) + lane * 2;
        float2 a0 = __half22float2(u0[0]), a1 = __half22float2(u0[1]);
        float2 b0 = __half22float2(u1[0]), b1 = __half22float2(u1[1]);
        acc.x = fmaf(w0, a0.x, acc.x); acc.y = fmaf(w0, a0.y, acc.y);
        acc.z = fmaf(w0, a1.x, acc.z); acc.w = fmaf(w0, a1.y, acc.w);
        acc.x = fmaf(w1, b0.x, acc.x); acc.y = fmaf(w1, b0.y, acc.y);
        acc.z = fmaf(w1, b1.x, acc.z); acc.w = fmaf(w1, b1.y, acc.w);
    }
    if (e < end) {
        int c0 = g_col[e];
        float w0 = g_dinv[c0] * dv;
        const __half2* u0 = (const __half2*)(hw + (size_t)c0 * HID) + lane * 2;
        float2 a0 = __half22float2(u0[0]), a1 = __half22float2(u0[1]);
        acc.x = fmaf(w0, a0.x, acc.x); acc.y = fmaf(w0, a0.y, acc.y);
        acc.z = fmaf(w0, a1.x, acc.z); acc.w = fmaf(w0, a1.y, acc.w);
    }

    float4 b = ((const float4*)bias)[lane];
    acc.x += b.x; acc.y += b.y; acc.z += b.z; acc.w += b.w;
    if (relu) {
        acc.x = fmaxf(acc.x, 0.f); acc.y = fmaxf(acc.y, 0.f);
        acc.z = fmaxf(acc.z, 0.f); acc.w = fmaxf(acc.w, 0.f);
    }
    ((float4*)(out + (size_t)node * HID))[lane] = acc;
}

// ------------------------- driver --------------------------------------------
extern "C" void kernel_launch(void* const* d_in, const int* in_sizes, int n_in,
                              void* d_out, int out_size) {
    const float* x_user    = (const float*)d_in[0];
    const float* x_item    = (const float*)d_in[1];
    const int*   edge_ui   = (const int*)d_in[2];
    const int*   edge_iu   = (const int*)d_in[3];
    const float* W_in_user = (const float*)d_in[4];
    const float* b_in_user = (const float*)d_in[5];
    const float* W_in_item = (const float*)d_in[6];
    const float* b_in_item = (const float*)d_in[7];
    const float* W1        = (const float*)d_in[8];
    const float* b1        = (const float*)d_in[9];
    const float* W2        = (const float*)d_in[10];
    const float* b2        = (const float*)d_in[11];
    float* out = (float*)d_out;

    float* h; __half* hw16;
    __nv_bfloat16* wt_hi; __nv_bfloat16* wt_lo;
    float* bfold;
    cudaGetSymbolAddress((void**)&h,     g_h);
    cudaGetSymbolAddress((void**)&hw16,  g_hw16);
    cudaGetSymbolAddress((void**)&wt_hi, g_wt_hi);
    cudaGetSymbolAddress((void**)&wt_lo, g_wt_lo);
    cudaGetSymbolAddress((void**)&bfold, g_bfold);

    const int SMEM_K256 = 2 * 128 * (256 + 8) * 2 + 4 * 6144;  // 159744
    const int SMEM_K128 = 2 * 128 * (128 + 8) * 2 + 4 * 6144;  // 94208
    cudaFuncSetAttribute(gemm_mma<256, true>,
                         cudaFuncAttributeMaxDynamicSharedMemorySize, SMEM_K256);
    cudaFuncSetAttribute(gemm_mma<128, false>,
                         cudaFuncAttributeMaxDynamicSharedMemorySize, SMEM_K128);

    const int NB_SCAN = (NNODE + 1023) / 1024;  // 196

    // CSR build + weight prep
    zero_deg<<<(NNODE + 255) / 256, 256>>>();
    build_deg<<<(E_TOT + 255) / 256, 256>>>(edge_ui, edge_iu);
    fold_weights<<<(2 * 256 * 128 + 255) / 256, 256>>>(W_in_user, W_in_item, W1);
    fold_bias<<<1, 128>>>(b_in_user, b_in_item, W1);
    conv_w2<<<(128 * 128 + 255) / 256, 256>>>(W2);
    scan1<<<NB_SCAN, 1024>>>();
    scan2<<<1, 32>>>(NB_SCAN);
    scan3<<<NB_SCAN, 1024>>>();
    fill_csr<<<(E_TOT + 255) / 256, 256>>>(edge_ui, edge_iu);

    // fused proj+W1 GEMMs -> hw1 (fp16)
    gemm_mma<256, true><<<(N_USER + 127) / 128, 256, SMEM_K256>>>(
        x_user, wt_hi + WT_WU, wt_lo + WT_WU, bfold, hw16, N_USER);
    gemm_mma<256, true><<<(N_ITEM + 127) / 128, 256, SMEM_K256>>>(
        x_item, wt_hi + WT_WI, wt_lo + WT_WI, bfold + HID,
        hw16 + (size_t)N_USER * HID, N_ITEM);

    // layer 1 aggregate: h = relu(agg(hw1) + b1)
    aggregate<<<(NNODE * 32 + 255) / 256, 256>>>(hw16, h, b1, 1);

    // layer 2: hw2 = h @ W2 (fp16), out = agg(hw2) + b2
    gemm_mma<128, false><<<(NNODE + 127) / 128, 256, SMEM_K128>>>(
        h, wt_hi + WT_W2, wt_lo + WT_W2, nullptr, hw16, NNODE);
    aggregate<<<(NNODE * 32 + 255) / 256, 256>>>(hw16, out, b2, 0);
}

// round 8
// speedup vs baseline: 2.5940x; 1.1615x over previous
#include <cuda_runtime.h>
#include <cuda_fp16.h>
#include <math.h>
#include <stdint.h>
#include <string.h>

#define N_USER 100000
#define N_ITEM 100000
#define NNODE  200000
#define E_HALF 600000
#define E_TOT  1200000
#define HID 128

// ------------------------- scratch (device globals, no alloc) ----------------
__device__ __half g_hw16[(size_t)NNODE * HID];   // pre-aggregation features (both layers)
__device__ __half g_h16[(size_t)NNODE * HID];    // layer-1 activations (fp16)
__device__ float  g_dinv[NNODE];
__device__ int    g_deg[NNODE];
__device__ int    g_rowptr[NNODE + 1];
__device__ int    g_cursor[NNODE];
__device__ int    g_col[E_TOT];
__device__ int    g_bsums[256];
__device__ float  g_bfold[2][HID];               // b_in @ W1 per node type

// fp16 hi/lo planes of weights, transposed Wt[n][k]:
//   folded user (128x256) at 0, folded item (128x256) at 32768, W2 (128x128) at 65536
#define WT_WU 0
#define WT_WI 32768
#define WT_W2 65536
__device__ __half g_wt_hi[81920];
__device__ __half g_wt_lo[81920];

// ------------------------- helpers -------------------------------------------
__device__ __forceinline__ uint32_t smem_u32(const void* p) {
    uint32_t a;
    asm("{ .reg .u64 t; cvta.to.shared.u64 t, %1; cvt.u32.u64 %0, t; }" : "=r"(a) : "l"(p));
    return a;
}

__device__ __forceinline__ uint32_t h2_as_u32(__half2 h) {
    uint32_t u;
    memcpy(&u, &h, 4);
    return u;
}

__device__ __forceinline__ void ldsm_x4(uint32_t& r0, uint32_t& r1,
                                        uint32_t& r2, uint32_t& r3, uint32_t addr) {
    asm volatile("ldmatrix.sync.aligned.m8n8.x4.shared.b16 {%0,%1,%2,%3}, [%4];"
                 : "=r"(r0), "=r"(r1), "=r"(r2), "=r"(r3) : "r"(addr));
}

__device__ __forceinline__ void mma16816(float* c, const uint32_t* a, const uint32_t* b) {
    asm volatile("mma.sync.aligned.m16n8k16.row.col.f32.f16.f16.f32 "
                 "{%0,%1,%2,%3}, {%4,%5,%6,%7}, {%8,%9}, {%0,%1,%2,%3};"
                 : "+f"(c[0]), "+f"(c[1]), "+f"(c[2]), "+f"(c[3])
                 : "r"(a[0]), "r"(a[1]), "r"(a[2]), "r"(a[3]), "r"(b[0]), "r"(b[1]));
}

// ------------------------- CSR build ------------------------------------------
__global__ void zero_deg() {
    int i = blockIdx.x * blockDim.x + threadIdx.x;
    if (i < NNODE) g_deg[i] = 0;
}

__global__ void build_deg(const int* __restrict__ eui, const int* __restrict__ eiu) {
    int i = blockIdx.x * blockDim.x + threadIdx.x;
    if (i < E_HALF) {
        atomicAdd(&g_deg[eui[E_HALF + i] + N_USER], 1);
    } else if (i < E_TOT) {
        atomicAdd(&g_deg[eiu[E_HALF + (i - E_HALF)]], 1);
    }
}

__global__ void scan1() {
    __shared__ int sm[1024];
    int tx = threadIdx.x;
    int i = blockIdx.x * 1024 + tx;
    int v = (i < NNODE) ? g_deg[i] : 0;
    sm[tx] = v;
    __syncthreads();
    #pragma unroll
    for (int off = 1; off < 1024; off <<= 1) {
        int t = (tx >= off) ? sm[tx - off] : 0;
        __syncthreads();
        sm[tx] += t;
        __syncthreads();
    }
    if (i < NNODE) g_rowptr[i] = sm[tx] - v;
    if (tx == 1023) g_bsums[blockIdx.x] = sm[1023];
}

__global__ void scan2(int nb) {
    if (threadIdx.x == 0 && blockIdx.x == 0) {
        int run = 0;
        for (int b = 0; b < nb; b++) { int v = g_bsums[b]; g_bsums[b] = run; run += v; }
    }
}

__global__ void scan3() {   // also computes dinv
    int tx = threadIdx.x;
    int i = blockIdx.x * 1024 + tx;
    if (i < NNODE) {
        int v = g_rowptr[i] + g_bsums[blockIdx.x];
        g_rowptr[i] = v;
        g_cursor[i] = v;
        g_dinv[i] = rsqrtf((float)(g_deg[i] + 1));
    }
    if (i == 0) g_rowptr[NNODE] = E_TOT;
}

__global__ void fill_csr(const int* __restrict__ eui, const int* __restrict__ eiu) {
    int i = blockIdx.x * blockDim.x + threadIdx.x;
    int s, d;
    if (i < E_HALF) {
        s = eui[i];
        d = eui[E_HALF + i] + N_USER;
    } else if (i < E_TOT) {
        int j = i - E_HALF;
        s = eiu[j] + N_USER;
        d = eiu[E_HALF + j];
    } else return;
    int pos = atomicAdd(&g_cursor[d], 1);
    g_col[pos] = s;
}

// ------------------------- weight prep ----------------------------------------
// Wfold[k][n] = sum_j W_in[k][j] * W1[j][n] -> fp16 hi/lo transposed at [n][k]
__global__ void fold_weights(const float* __restrict__ Wu, const float* __restrict__ Wi,
                             const float* __restrict__ W1) {
    int i = blockIdx.x * blockDim.x + threadIdx.x;   // 2*256*128
    if (i >= 2 * 256 * 128) return;
    int type = i >> 15;
    int k = (i >> 7) & 255;
    int n = i & 127;
    const float* Win = type ? Wi : Wu;
    float s = 0.f;
    #pragma unroll 8
    for (int j = 0; j < 128; j++)
        s = fmaf(Win[(size_t)k * 128 + j], W1[(size_t)j * 128 + n], s);
    __half hi = __float2half_rn(s);
    __half lo = __float2half_rn(s - __half2float(hi));
    int dst = (type ? WT_WI : WT_WU) + n * 256 + k;
    g_wt_hi[dst] = hi;
    g_wt_lo[dst] = lo;
}

// one warp per output (2 types x 128 n) = 256 warps
__global__ void fold_bias(const float* __restrict__ bu, const float* __restrict__ bi,
                          const float* __restrict__ W1) {
    int w = (blockIdx.x * blockDim.x + threadIdx.x) >> 5;   // 0..255
    int lane = threadIdx.x & 31;
    if (w >= 256) return;
    int type = w >> 7, n = w & 127;
    const float* b = type ? bi : bu;
    float s = 0.f;
    #pragma unroll
    for (int q = 0; q < 4; q++) {
        int j = lane + q * 32;
        s = fmaf(b[j], W1[(size_t)j * 128 + n], s);
    }
    #pragma unroll
    for (int off = 16; off > 0; off >>= 1)
        s += __shfl_down_sync(0xffffffff, s, off);
    if (lane == 0) g_bfold[type][n] = s;
}

__global__ void conv_w2(const float* __restrict__ W2) {
    int i = blockIdx.x * blockDim.x + threadIdx.x;   // 128*128
    if (i >= 128 * 128) return;
    int k = i >> 7, n = i & 127;
    float w = W2[(size_t)k * 128 + n];
    __half hi = __float2half_rn(w);
    __half lo = __float2half_rn(w - __half2float(hi));
    int dst = WT_W2 + n * 128 + k;
    g_wt_hi[dst] = hi;
    g_wt_lo[dst] = lo;
}

// ------------------------- HMMA GEMM: C[M,128] = A[M,K] @ W[K,128] ------------
// A fp16 (exact), W split fp16 hi/lo -> 2 MMA products, fp32 accum, fp16 out.
// AT = float (convert on load) or __half (raw copy).
template <int K, bool BIAS, typename AT>
__global__ __launch_bounds__(256) void gemm_mma(
    const AT* __restrict__ A, const __half* __restrict__ Wt_hi,
    const __half* __restrict__ Wt_lo, const float* __restrict__ bias,
    __half* __restrict__ C, int M)
{
    constexpr int WSTRIDE = (K + 8) * 2;   // bytes per W smem row
    constexpr int WBYTES  = 128 * WSTRIDE;
    constexpr int ASTRIDE = 48;            // bytes per A smem row (32B data + 16 pad)
    constexpr int ABYTES  = 128 * ASTRIDE; // 6144
    constexpr int NCH     = K / 16;

    extern __shared__ char smem[];
    char* sWhi = smem;
    char* sWlo = smem + WBYTES;
    char* sA   = smem + 2 * WBYTES;        // 2 double-buffered A planes

    const int tid = threadIdx.x, lane = tid & 31, wid = tid >> 5;
    const int m0 = (wid >> 2) * 64, n0 = (wid & 3) * 32;
    const int block_row = blockIdx.x * 128;

    const uint32_t sWhi_u = smem_u32(sWhi);
    const uint32_t sWlo_u = smem_u32(sWlo);
    const uint32_t sA_u   = smem_u32(sA);

    // stage W planes
    {
        const uint32_t* wh = (const uint32_t*)Wt_hi;
        const uint32_t* wl = (const uint32_t*)Wt_lo;
        #pragma unroll 4
        for (int i = tid; i < 128 * (K / 2); i += 256) {
            int n = i / (K / 2), kp = i % (K / 2);
            *(uint32_t*)(sWhi + n * WSTRIDE + kp * 4) = wh[i];
            *(uint32_t*)(sWlo + n * WSTRIDE + kp * 4) = wl[i];
        }
    }

    float acc[4][4][4];
    #pragma unroll
    for (int a = 0; a < 4; a++)
        #pragma unroll
        for (int b = 0; b < 4; b++)
            #pragma unroll
            for (int c = 0; c < 4; c++) acc[a][b][c] = 0.f;

    const uint32_t aoff = (uint32_t)((lane & 15) * ASTRIDE + ((lane & 16) ? 16 : 0));
    const uint32_t woff = (uint32_t)((((lane & 16) ? 8 : 0) + (lane & 7)) * WSTRIDE +
                                     ((lane & 8) ? 16 : 0));

    // staging state
    float4 vf[2];      // float path
    uint4  vh;         // half path
    const int fr0 = tid >> 2, fp0 = tid & 3;        // float: 2 quarters/thread
    const int fr1 = (tid + 256) >> 2;
    const int hr = tid >> 1, hp = tid & 1;          // half: 1 half-row/thread

    auto load_tile = [&](int ck) {
        if constexpr (sizeof(AT) == 4) {
            int row0 = block_row + fr0, row1 = block_row + fr1;
            vf[0] = (row0 < M) ? *(const float4*)((const float*)A + (size_t)row0 * K + ck * 16 + fp0 * 4)
                               : make_float4(0.f, 0.f, 0.f, 0.f);
            vf[1] = (row1 < M) ? *(const float4*)((const float*)A + (size_t)row1 * K + ck * 16 + fp0 * 4)
                               : make_float4(0.f, 0.f, 0.f, 0.f);
        } else {
            int row = block_row + hr;
            vh = (row < M) ? *(const uint4*)((const __half*)A + (size_t)row * K + ck * 16 + hp * 8)
                           : make_uint4(0, 0, 0, 0);
        }
    };
    auto store_tile = [&](int db) {
        char* buf = sA + db * ABYTES;
        if constexpr (sizeof(AT) == 4) {
            #pragma unroll
            for (int q = 0; q < 2; q++) {
                int r = q ? fr1 : fr0;
                uint2 o;
                o.x = h2_as_u32(__floats2half2_rn(vf[q].x, vf[q].y));
                o.y = h2_as_u32(__floats2half2_rn(vf[q].z, vf[q].w));
                *(uint2*)(buf + r * ASTRIDE + fp0 * 8) = o;
            }
        } else {
            *(uint4*)(buf + hr * ASTRIDE + hp * 16) = vh;
        }
    };

    load_tile(0);
    store_tile(0);
    __syncthreads();

    for (int ck = 0; ck < NCH; ck++) {
        if (ck + 1 < NCH) load_tile(ck + 1);

        const uint32_t abase = sA_u + (ck & 1) * ABYTES;
        const uint32_t wk = (uint32_t)(n0 * WSTRIDE + ck * 32) + woff;

        uint32_t wh[4][2], wl[4][2], af[4][4];
        #pragma unroll
        for (int nt2 = 0; nt2 < 2; nt2++) {
            uint32_t q0, q1, q2, q3;
            ldsm_x4(q0, q1, q2, q3, sWhi_u + wk + nt2 * 16 * WSTRIDE);
            wh[nt2 * 2 + 0][0] = q0; wh[nt2 * 2 + 0][1] = q1;
            wh[nt2 * 2 + 1][0] = q2; wh[nt2 * 2 + 1][1] = q3;
            ldsm_x4(q0, q1, q2, q3, sWlo_u + wk + nt2 * 16 * WSTRIDE);
            wl[nt2 * 2 + 0][0] = q0; wl[nt2 * 2 + 0][1] = q1;
            wl[nt2 * 2 + 1][0] = q2; wl[nt2 * 2 + 1][1] = q3;
        }
        #pragma unroll
        for (int mt = 0; mt < 4; mt++)
            ldsm_x4(af[mt][0], af[mt][1], af[mt][2], af[mt][3],
                    abase + (uint32_t)((m0 + mt * 16) * ASTRIDE) + aoff);

        #pragma unroll
        for (int mt = 0; mt < 4; mt++)
            #pragma unroll
            for (int nt = 0; nt < 4; nt++)
                mma16816(acc[mt][nt], af[mt], wh[nt]);
        #pragma unroll
        for (int mt = 0; mt < 4; mt++)
            #pragma unroll
            for (int nt = 0; nt < 4; nt++)
                mma16816(acc[mt][nt], af[mt], wl[nt]);

        __syncthreads();
        if (ck + 1 < NCH) {
            store_tile((ck + 1) & 1);
            __syncthreads();
        }
    }

    // epilogue: fp16 out
    #pragma unroll
    for (int nt = 0; nt < 4; nt++) {
        int col = n0 + nt * 8 + 2 * (lane & 3);
        float b0 = 0.f, b1 = 0.f;
        if (BIAS) { b0 = bias[col]; b1 = bias[col + 1]; }
        #pragma unroll
        for (int mt = 0; mt < 4; mt++) {
            int row = block_row + m0 + mt * 16 + (lane >> 2);
            if (row < M)
                *(__half2*)(C + (size_t)row * 128 + col) =
                    __floats2half2_rn(acc[mt][nt][0] + b0, acc[mt][nt][1] + b1);
            if (row + 8 < M)
                *(__half2*)(C + (size_t)(row + 8) * 128 + col) =
                    __floats2half2_rn(acc[mt][nt][2] + b0, acc[mt][nt][3] + b1);
        }
    }
}

// ------------------------- aggregation: one warp per dst node ----------------
template <typename OUTT>
__global__ __launch_bounds__(256)
void aggregate(const __half* __restrict__ hw, OUTT* __restrict__ out,
               const float* __restrict__ bias, int relu) {
    int node = (blockIdx.x * blockDim.x + threadIdx.x) >> 5;
    int lane = threadIdx.x & 31;
    if (node >= NNODE) return;

    float dv = g_dinv[node];
    float ws = dv * dv;

    const __half2* self = (const __half2*)(hw + (size_t)node * HID) + lane * 2;
    float2 s0 = __half22float2(self[0]);
    float2 s1 = __half22float2(self[1]);
    float4 acc = make_float4(s0.x * ws, s0.y * ws, s1.x * ws, s1.y * ws);

    int e = g_rowptr[node];
    int end = g_rowptr[node + 1];
    for (; e + 1 < end; e += 2) {
        int c0 = g_col[e], c1 = g_col[e + 1];
        float w0 = g_dinv[c0] * dv;
        float w1 = g_dinv[c1] * dv;
        const __half2* u0 = (const __half2*)(hw + (size_t)c0 * HID) + lane * 2;
        const __half2* u1 = (const __half2*)(hw + (size_t)c1 * HID) + lane * 2;
        float2 a0 = __half22float2(u0[0]), a1 = __half22float2(u0[1]);
        float2 b0 = __half22float2(u1[0]), b1 = __half22float2(u1[1]);
        acc.x = fmaf(w0, a0.x, acc.x); acc.y = fmaf(w0, a0.y, acc.y);
        acc.z = fmaf(w0, a1.x, acc.z); acc.w = fmaf(w0, a1.y, acc.w);
        acc.x = fmaf(w1, b0.x, acc.x); acc.y = fmaf(w1, b0.y, acc.y);
        acc.z = fmaf(w1, b1.x, acc.z); acc.w = fmaf(w1, b1.y, acc.w);
    }
    if (e < end) {
        int c0 = g_col[e];
        float w0 = g_dinv[c0] * dv;
        const __half2* u0 = (const __half2*)(hw + (size_t)c0 * HID) + lane * 2;
        float2 a0 = __half22float2(u0[0]), a1 = __half22float2(u0[1]);
        acc.x = fmaf(w0, a0.x, acc.x); acc.y = fmaf(w0, a0.y, acc.y);
        acc.z = fmaf(w0, a1.x, acc.z); acc.w = fmaf(w0, a1.y, acc.w);
    }

    float4 b = ((const float4*)bias)[lane];
    acc.x += b.x; acc.y += b.y; acc.z += b.z; acc.w += b.w;
    if (relu) {
        acc.x = fmaxf(acc.x, 0.f); acc.y = fmaxf(acc.y, 0.f);
        acc.z = fmaxf(acc.z, 0.f); acc.w = fmaxf(acc.w, 0.f);
    }
    if constexpr (sizeof(OUTT) == 4) {
        ((float4*)((float*)out + (size_t)node * HID))[lane] = acc;
    } else {
        __half2* op = (__half2*)((__half*)out + (size_t)node * HID) + lane * 2;
        op[0] = __floats2half2_rn(acc.x, acc.y);
        op[1] = __floats2half2_rn(acc.z, acc.w);
    }
}

// ------------------------- driver --------------------------------------------
extern "C" void kernel_launch(void* const* d_in, const int* in_sizes, int n_in,
                              void* d_out, int out_size) {
    const float* x_user    = (const float*)d_in[0];
    const float* x_item    = (const float*)d_in[1];
    const int*   edge_ui   = (const int*)d_in[2];
    const int*   edge_iu   = (const int*)d_in[3];
    const float* W_in_user = (const float*)d_in[4];
    const float* b_in_user = (const float*)d_in[5];
    const float* W_in_item = (const float*)d_in[6];
    const float* b_in_item = (const float*)d_in[7];
    const float* W1        = (const float*)d_in[8];
    const float* b1        = (const float*)d_in[9];
    const float* W2        = (const float*)d_in[10];
    const float* b2        = (const float*)d_in[11];
    float* out = (float*)d_out;

    __half* hw16; __half* h16;
    __half* wt_hi; __half* wt_lo;
    float* bfold;
    cudaGetSymbolAddress((void**)&hw16,  g_hw16);
    cudaGetSymbolAddress((void**)&h16,   g_h16);
    cudaGetSymbolAddress((void**)&wt_hi, g_wt_hi);
    cudaGetSymbolAddress((void**)&wt_lo, g_wt_lo);
    cudaGetSymbolAddress((void**)&bfold, g_bfold);

    const int SMEM_K256 = 2 * 128 * (256 + 8) * 2 + 2 * 6144;  // 147456
    const int SMEM_K128 = 2 * 128 * (128 + 8) * 2 + 2 * 6144;  // 81920
    cudaFuncSetAttribute((const void*)gemm_mma<256, true, float>,
                         cudaFuncAttributeMaxDynamicSharedMemorySize, SMEM_K256);
    cudaFuncSetAttribute((const void*)gemm_mma<128, false, __half>,
                         cudaFuncAttributeMaxDynamicSharedMemorySize, SMEM_K128);

    const int NB_SCAN = (NNODE + 1023) / 1024;  // 196

    // CSR build + weight prep
    zero_deg<<<(NNODE + 255) / 256, 256>>>();
    build_deg<<<(E_TOT + 255) / 256, 256>>>(edge_ui, edge_iu);
    fold_weights<<<(2 * 256 * 128 + 255) / 256, 256>>>(W_in_user, W_in_item, W1);
    fold_bias<<<32, 256>>>(b_in_user, b_in_item, W1);
    conv_w2<<<(128 * 128 + 255) / 256, 256>>>(W2);
    scan1<<<NB_SCAN, 1024>>>();
    scan2<<<1, 32>>>(NB_SCAN);
    scan3<<<NB_SCAN, 1024>>>();
    fill_csr<<<(E_TOT + 255) / 256, 256>>>(edge_ui, edge_iu);

    // fused proj+W1 GEMMs -> hw1 (fp16)
    gemm_mma<256, true, float><<<(N_USER + 127) / 128, 256, SMEM_K256>>>(
        x_user, wt_hi + WT_WU, wt_lo + WT_WU, bfold, hw16, N_USER);
    gemm_mma<256, true, float><<<(N_ITEM + 127) / 128, 256, SMEM_K256>>>(
        x_item, wt_hi + WT_WI, wt_lo + WT_WI, bfold + HID,
        hw16 + (size_t)N_USER * HID, N_ITEM);

    // layer 1 aggregate: h16 = relu(agg(hw1) + b1)  (fp16)
    aggregate<__half><<<(NNODE * 32 + 255) / 256, 256>>>(hw16, h16, b1, 1);

    // layer 2: hw2 = h16 @ W2 (fp16 in/out), out = agg(hw2) + b2 (fp32)
    gemm_mma<128, false, __half><<<(NNODE + 127) / 128, 256, SMEM_K128>>>(
        h16, wt_hi + WT_W2, wt_lo + WT_W2, nullptr, hw16, NNODE);
    aggregate<float><<<(NNODE * 32 + 255) / 256, 256>>>(hw16, out, b2, 0);
}

// round 10
// speedup vs baseline: 3.0340x; 1.1696x over previous
#include <cuda_runtime.h>
#include <cuda_fp16.h>
#include <math.h>
#include <stdint.h>
#include <string.h>

#define N_USER 100000
#define N_ITEM 100000
#define NNODE  200000
#define E_HALF 600000
#define E_TOT  1200000
#define HID 128

// ------------------------- scratch (device globals, no alloc) ----------------
__device__ __half g_hw16[(size_t)NNODE * HID];   // pre-aggregation features (both layers)
__device__ __half g_h16[(size_t)NNODE * HID];    // layer-1 activations (fp16)
__device__ float  g_dinv[NNODE];
__device__ int    g_deg[NNODE];
__device__ int    g_rowptr[NNODE + 1];
__device__ int    g_cursor[NNODE];
__device__ int    g_col[E_TOT];
__device__ int    g_bsums[256];
__device__ float  g_bfold[2][HID];               // b_in @ W1 per node type

// fp16 hi/lo planes of weights, transposed Wt[n][k]:
//   folded user (128x256) at 0, folded item (128x256) at 32768, W2 (128x128) at 65536
#define WT_WU 0
#define WT_WI 32768
#define WT_W2 65536
__device__ __half g_wt_hi[81920];
__device__ __half g_wt_lo[81920];

// ------------------------- helpers -------------------------------------------
__device__ __forceinline__ uint32_t smem_u32(const void* p) {
    uint32_t a;
    asm("{ .reg .u64 t; cvta.to.shared.u64 t, %1; cvt.u32.u64 %0, t; }" : "=r"(a) : "l"(p));
    return a;
}

__device__ __forceinline__ uint32_t h2_as_u32(__half2 h) {
    uint32_t u;
    memcpy(&u, &h, 4);
    return u;
}

__device__ __forceinline__ void ldsm_x4(uint32_t& r0, uint32_t& r1,
                                        uint32_t& r2, uint32_t& r3, uint32_t addr) {
    asm volatile("ldmatrix.sync.aligned.m8n8.x4.shared.b16 {%0,%1,%2,%3}, [%4];"
                 : "=r"(r0), "=r"(r1), "=r"(r2), "=r"(r3) : "r"(addr));
}

__device__ __forceinline__ void mma16816(float* c, const uint32_t* a, const uint32_t* b) {
    asm volatile("mma.sync.aligned.m16n8k16.row.col.f32.f16.f16.f32 "
                 "{%0,%1,%2,%3}, {%4,%5,%6,%7}, {%8,%9}, {%0,%1,%2,%3};"
                 : "+f"(c[0]), "+f"(c[1]), "+f"(c[2]), "+f"(c[3])
                 : "r"(a[0]), "r"(a[1]), "r"(a[2]), "r"(a[3]), "r"(b[0]), "r"(b[1]));
}

// ------------------------- fused prep: zero_deg + weight fold/convert ---------
// blocks [0,256): fold_weights; [256,320): conv_w2; [320,352): fold_bias;
// blocks [352,1134): zero_deg
__global__ void prep_all(const float* __restrict__ Wu, const float* __restrict__ Wi,
                         const float* __restrict__ W1, const float* __restrict__ W2,
                         const float* __restrict__ bu, const float* __restrict__ bi) {
    int blk = blockIdx.x, tid = threadIdx.x;
    if (blk < 256) {
        // fold: Wfold[k][n] = sum_j W_in[k][j] * W1[j][n], store [n][k] hi/lo
        int i = blk * 256 + tid;                 // < 65536
        int type = i >> 15;
        int k = (i >> 7) & 255;
        int n = i & 127;
        const float* Win = type ? Wi : Wu;
        float s = 0.f;
        #pragma unroll 8
        for (int j = 0; j < 128; j++)
            s = fmaf(Win[(size_t)k * 128 + j], W1[(size_t)j * 128 + n], s);
        __half hi = __float2half_rn(s);
        __half lo = __float2half_rn(s - __half2float(hi));
        int dst = (type ? WT_WI : WT_WU) + n * 256 + k;
        g_wt_hi[dst] = hi;
        g_wt_lo[dst] = lo;
    } else if (blk < 320) {
        int i = (blk - 256) * 256 + tid;         // < 16384
        int k = i >> 7, n = i & 127;
        float w = W2[(size_t)k * 128 + n];
        __half hi = __float2half_rn(w);
        __half lo = __float2half_rn(w - __half2float(hi));
        int dst = WT_W2 + n * 128 + k;
        g_wt_hi[dst] = hi;
        g_wt_lo[dst] = lo;
    } else if (blk < 352) {
        int w = (blk - 320) * 8 + (tid >> 5);    // < 256 warps
        int lane = tid & 31;
        int type = w >> 7, n = w & 127;
        const float* b = type ? bi : bu;
        float s = 0.f;
        #pragma unroll
        for (int q = 0; q < 4; q++) {
            int j = lane + q * 32;
            s = fmaf(b[j], W1[(size_t)j * 128 + n], s);
        }
        #pragma unroll
        for (int off = 16; off > 0; off >>= 1)
            s += __shfl_down_sync(0xffffffff, s, off);
        if (lane == 0) g_bfold[type][n] = s;
    } else {
        int i = (blk - 352) * 256 + tid;
        if (i < NNODE) g_deg[i] = 0;
    }
}

// ------------------------- CSR build ------------------------------------------
__global__ void build_deg(const int* __restrict__ eui, const int* __restrict__ eiu) {
    int i = blockIdx.x * blockDim.x + threadIdx.x;
    if (i < E_HALF) {
        atomicAdd(&g_deg[eui[E_HALF + i] + N_USER], 1);
    } else if (i < E_TOT) {
        atomicAdd(&g_deg[eiu[E_HALF + (i - E_HALF)]], 1);
    }
}

__global__ void scan1() {
    __shared__ int sm[1024];
    int tx = threadIdx.x;
    int i = blockIdx.x * 1024 + tx;
    int v = (i < NNODE) ? g_deg[i] : 0;
    sm[tx] = v;
    __syncthreads();
    #pragma unroll
    for (int off = 1; off < 1024; off <<= 1) {
        int t = (tx >= off) ? sm[tx - off] : 0;
        __syncthreads();
        sm[tx] += t;
        __syncthreads();
    }
    if (i < NNODE) g_rowptr[i] = sm[tx] - v;
    if (tx == 1023) g_bsums[blockIdx.x] = sm[1023];
}

__global__ void scan2k() {   // one block, 256 threads, exclusive scan of 196 sums
    __shared__ int sm[256];
    int tx = threadIdx.x;
    int v = (tx < 196) ? g_bsums[tx] : 0;
    sm[tx] = v;
    __syncthreads();
    #pragma unroll
    for (int off = 1; off < 256; off <<= 1) {
        int t = (tx >= off) ? sm[tx - off] : 0;
        __syncthreads();
        sm[tx] += t;
        __syncthreads();
    }
    if (tx < 196) g_bsums[tx] = sm[tx] - v;
}

__global__ void scan3() {   // also computes dinv
    int tx = threadIdx.x;
    int i = blockIdx.x * 1024 + tx;
    if (i < NNODE) {
        int v = g_rowptr[i] + g_bsums[blockIdx.x];
        g_rowptr[i] = v;
        g_cursor[i] = v;
        g_dinv[i] = rsqrtf((float)(g_deg[i] + 1));
    }
    if (i == 0) g_rowptr[NNODE] = E_TOT;
}

__global__ void fill_csr(const int* __restrict__ eui, const int* __restrict__ eiu) {
    int i = blockIdx.x * blockDim.x + threadIdx.x;
    int s, d;
    if (i < E_HALF) {
        s = eui[i];
        d = eui[E_HALF + i] + N_USER;
    } else if (i < E_TOT) {
        int j = i - E_HALF;
        s = eiu[j] + N_USER;
        d = eiu[E_HALF + j];
    } else return;
    int pos = atomicAdd(&g_cursor[d], 1);
    g_col[pos] = s;
}

// ------------------------- HMMA GEMM: C[M,128] = A[M,K] @ W[K,128] ------------
// A fp16 (exact), W split fp16 hi/lo -> 2 MMA products, fp32 accum, fp16 out.
// W is resident per 128-K half (restaged for K=256): smem 80KB -> 2 CTAs/SM.
// Single __syncthreads per K-chunk.
template <int K, bool BIAS, typename AT>
__global__ __launch_bounds__(256) void gemm_mma(
    const AT* __restrict__ A, const __half* __restrict__ Wt_hi,
    const __half* __restrict__ Wt_lo, const float* __restrict__ bias,
    __half* __restrict__ C, int M)
{
    constexpr int WSTRIDE = 272;           // bytes per W smem row (128 halves + 8 pad)
    constexpr int WBYTES  = 128 * WSTRIDE; // 34816 per plane
    constexpr int ASTRIDE = 48;            // bytes per A smem row (16 halves + 8 pad)
    constexpr int ABYTES  = 128 * ASTRIDE; // 6144
    constexpr int NCH     = K / 16;

    extern __shared__ char smem[];
    char* sWhi = smem;
    char* sWlo = smem + WBYTES;
    char* sA   = smem + 2 * WBYTES;        // 2 double-buffered A planes

    const int tid = threadIdx.x, lane = tid & 31, wid = tid >> 5;
    const int m0 = (wid >> 2) * 64, n0 = (wid & 3) * 32;
    const int block_row = blockIdx.x * 128;

    const uint32_t sWhi_u = smem_u32(sWhi);
    const uint32_t sWlo_u = smem_u32(sWlo);
    const uint32_t sA_u   = smem_u32(sA);

    // stage one 128-K half of both W planes
    auto stage_w = [&](int kh) {
        const uint32_t* wh = (const uint32_t*)Wt_hi;
        const uint32_t* wl = (const uint32_t*)Wt_lo;
        #pragma unroll 4
        for (int i = tid; i < 128 * 64; i += 256) {
            int n = i >> 6, kp = i & 63;
            int src = n * (K / 2) + kh * 64 + kp;
            *(uint32_t*)(sWhi + n * WSTRIDE + kp * 4) = wh[src];
            *(uint32_t*)(sWlo + n * WSTRIDE + kp * 4) = wl[src];
        }
    };

    float acc[4][4][4];
    #pragma unroll
    for (int a = 0; a < 4; a++)
        #pragma unroll
        for (int b = 0; b < 4; b++)
            #pragma unroll
            for (int c = 0; c < 4; c++) acc[a][b][c] = 0.f;

    const uint32_t aoff = (uint32_t)((lane & 15) * ASTRIDE + ((lane & 16) ? 16 : 0));
    const uint32_t woff = (uint32_t)((((lane & 16) ? 8 : 0) + (lane & 7)) * WSTRIDE +
                                     ((lane & 8) ? 16 : 0));

    // staging state
    float4 vf[2];      // float path
    uint4  vh;         // half path
    const int fr0 = tid >> 2, fp0 = tid & 3;        // float: 2 quarters/thread
    const int fr1 = (tid + 256) >> 2;
    const int hr = tid >> 1, hp = tid & 1;          // half: 1 half-row/thread

    auto load_tile = [&](int ck) {
        if constexpr (sizeof(AT) == 4) {
            int row0 = block_row + fr0, row1 = block_row + fr1;
            vf[0] = (row0 < M) ? *(const float4*)((const float*)A + (size_t)row0 * K + ck * 16 + fp0 * 4)
                               : make_float4(0.f, 0.f, 0.f, 0.f);
            vf[1] = (row1 < M) ? *(const float4*)((const float*)A + (size_t)row1 * K + ck * 16 + fp0 * 4)
                               : make_float4(0.f, 0.f, 0.f, 0.f);
        } else {
            int row = block_row + hr;
            vh = (row < M) ? *(const uint4*)((const __half*)A + (size_t)row * K + ck * 16 + hp * 8)
                           : make_uint4(0, 0, 0, 0);
        }
    };
    auto store_tile = [&](int db) {
        char* buf = sA + db * ABYTES;
        if constexpr (sizeof(AT) == 4) {
            #pragma unroll
            for (int q = 0; q < 2; q++) {
                int r = q ? fr1 : fr0;
                uint2 o;
                o.x = h2_as_u32(__floats2half2_rn(vf[q].x, vf[q].y));
                o.y = h2_as_u32(__floats2half2_rn(vf[q].z, vf[q].w));
                *(uint2*)(buf + r * ASTRIDE + fp0 * 8) = o;
            }
        } else {
            *(uint4*)(buf + hr * ASTRIDE + hp * 16) = vh;
        }
    };

    stage_w(0);
    load_tile(0);
    store_tile(0);
    __syncthreads();

    for (int ck = 0; ck < NCH; ck++) {
        if (ck + 1 < NCH) load_tile(ck + 1);

        const uint32_t abase = sA_u + (ck & 1) * ABYTES;
        const uint32_t wk = (uint32_t)(n0 * WSTRIDE + (ck & 7) * 32) + woff;

        uint32_t wh[4][2], wl[4][2], af[4][4];
        #pragma unroll
        for (int nt2 = 0; nt2 < 2; nt2++) {
            uint32_t q0, q1, q2, q3;
            ldsm_x4(q0, q1, q2, q3, sWhi_u + wk + nt2 * 16 * WSTRIDE);
            wh[nt2 * 2 + 0][0] = q0; wh[nt2 * 2 + 0][1] = q1;
            wh[nt2 * 2 + 1][0] = q2; wh[nt2 * 2 + 1][1] = q3;
            ldsm_x4(q0, q1, q2, q3, sWlo_u + wk + nt2 * 16 * WSTRIDE);
            wl[nt2 * 2 + 0][0] = q0; wl[nt2 * 2 + 0][1] = q1;
            wl[nt2 * 2 + 1][0] = q2; wl[nt2 * 2 + 1][1] = q3;
        }
        #pragma unroll
        for (int mt = 0; mt < 4; mt++)
            ldsm_x4(af[mt][0], af[mt][1], af[mt][2], af[mt][3],
                    abase + (uint32_t)((m0 + mt * 16) * ASTRIDE) + aoff);

        #pragma unroll
        for (int mt = 0; mt < 4; mt++)
            #pragma unroll
            for (int nt = 0; nt < 4; nt++)
                mma16816(acc[mt][nt], af[mt], wh[nt]);
        #pragma unroll
        for (int mt = 0; mt < 4; mt++)
            #pragma unroll
            for (int nt = 0; nt < 4; nt++)
                mma16816(acc[mt][nt], af[mt], wl[nt]);

        if (ck + 1 < NCH) store_tile((ck + 1) & 1);
        __syncthreads();

        if constexpr (K > 128) {
            if ((ck & 7) == 7 && ck + 1 < NCH) {
                stage_w((ck + 1) >> 3);
                __syncthreads();
            }
        }
    }

    // epilogue: fp16 out
    #pragma unroll
    for (int nt = 0; nt < 4; nt++) {
        int col = n0 + nt * 8 + 2 * (lane & 3);
        float b0 = 0.f, b1 = 0.f;
        if (BIAS) { b0 = bias[col]; b1 = bias[col + 1]; }
        #pragma unroll
        for (int mt = 0; mt < 4; mt++) {
            int row = block_row + m0 + mt * 16 + (lane >> 2);
            if (row < M)
                *(__half2*)(C + (size_t)row * 128 + col) =
                    __floats2half2_rn(acc[mt][nt][0] + b0, acc[mt][nt][1] + b1);
            if (row + 8 < M)
                *(__half2*)(C + (size_t)(row + 8) * 128 + col) =
                    __floats2half2_rn(acc[mt][nt][2] + b0, acc[mt][nt][3] + b1);
        }
    }
}

// ------------------------- aggregation: one warp per dst node ----------------
template <typename OUTT>
__global__ __launch_bounds__(256)
void aggregate(const __half* __restrict__ hw, OUTT* __restrict__ out,
               const float* __restrict__ bias, int relu) {
    int node = (blockIdx.x * blockDim.x + threadIdx.x) >> 5;
    int lane = threadIdx.x & 31;
    if (node >= NNODE) return;

    float dv = g_dinv[node];
    float ws = dv * dv;

    const __half2* self = (const __half2*)(hw + (size_t)node * HID) + lane * 2;
    float2 s0 = __half22float2(self[0]);
    float2 s1 = __half22float2(self[1]);
    float4 acc = make_float4(s0.x * ws, s0.y * ws, s1.x * ws, s1.y * ws);

    int e = g_rowptr[node];
    int end = g_rowptr[node + 1];
    for (; e + 1 < end; e += 2) {
        int c0 = g_col[e], c1 = g_col[e + 1];
        float w0 = g_dinv[c0] * dv;
        float w1 = g_dinv[c1] * dv;
        const __half2* u0 = (const __half2*)(hw + (size_t)c0 * HID) + lane * 2;
        const __half2* u1 = (const __half2*)(hw + (size_t)c1 * HID) + lane * 2;
        float2 a0 = __half22float2(u0[0]), a1 = __half22float2(u0[1]);
        float2 b0 = __half22float2(u1[0]), b1 = __half22float2(u1[1]);
        acc.x = fmaf(w0, a0.x, acc.x); acc.y = fmaf(w0, a0.y, acc.y);
        acc.z = fmaf(w0, a1.x, acc.z); acc.w = fmaf(w0, a1.y, acc.w);
        acc.x = fmaf(w1, b0.x, acc.x); acc.y = fmaf(w1, b0.y, acc.y);
        acc.z = fmaf(w1, b1.x, acc.z); acc.w = fmaf(w1, b1.y, acc.w);
    }
    if (e < end) {
        int c0 = g_col[e];
        float w0 = g_dinv[c0] * dv;
        const __half2* u0 = (const __half2*)(hw + (size_t)c0 * HID) + lane * 2;
        float2 a0 = __half22float2(u0[0]), a1 = __half22float2(u0[1]);
        acc.x = fmaf(w0, a0.x, acc.x); acc.y = fmaf(w0, a0.y, acc.y);
        acc.z = fmaf(w0, a1.x, acc.z); acc.w = fmaf(w0, a1.y, acc.w);
    }

    float4 b = ((const float4*)bias)[lane];
    acc.x += b.x; acc.y += b.y; acc.z += b.z; acc.w += b.w;
    if (relu) {
        acc.x = fmaxf(acc.x, 0.f); acc.y = fmaxf(acc.y, 0.f);
        acc.z = fmaxf(acc.z, 0.f); acc.w = fmaxf(acc.w, 0.f);
    }
    if constexpr (sizeof(OUTT) == 4) {
        ((float4*)((float*)out + (size_t)node * HID))[lane] = acc;
    } else {
        __half2* op = (__half2*)((__half*)out + (size_t)node * HID) + lane * 2;
        op[0] = __floats2half2_rn(acc.x, acc.y);
        op[1] = __floats2half2_rn(acc.z, acc.w);
    }
}

// ------------------------- driver --------------------------------------------
extern "C" void kernel_launch(void* const* d_in, const int* in_sizes, int n_in,
                              void* d_out, int out_size) {
    const float* x_user    = (const float*)d_in[0];
    const float* x_item    = (const float*)d_in[1];
    const int*   edge_ui   = (const int*)d_in[2];
    const int*   edge_iu   = (const int*)d_in[3];
    const float* W_in_user = (const float*)d_in[4];
    const float* b_in_user = (const float*)d_in[5];
    const float* W_in_item = (const float*)d_in[6];
    const float* b_in_item = (const float*)d_in[7];
    const float* W1        = (const float*)d_in[8];
    const float* b1        = (const float*)d_in[9];
    const float* W2        = (const float*)d_in[10];
    const float* b2        = (const float*)d_in[11];
    float* out = (float*)d_out;

    __half* hw16; __half* h16;
    __half* wt_hi; __half* wt_lo;
    float* bfold;
    cudaGetSymbolAddress((void**)&hw16,  g_hw16);
    cudaGetSymbolAddress((void**)&h16,   g_h16);
    cudaGetSymbolAddress((void**)&wt_hi, g_wt_hi);
    cudaGetSymbolAddress((void**)&wt_lo, g_wt_lo);
    cudaGetSymbolAddress((void**)&bfold, g_bfold);

    const int SMEM_GEMM = 2 * 34816 + 2 * 6144;   // 81920
    cudaFuncSetAttribute((const void*)gemm_mma<256, true, float>,
                         cudaFuncAttributeMaxDynamicSharedMemorySize, SMEM_GEMM);
    cudaFuncSetAttribute((const void*)gemm_mma<128, false, __half>,
                         cudaFuncAttributeMaxDynamicSharedMemorySize, SMEM_GEMM);

    const int NB_SCAN = (NNODE + 1023) / 1024;  // 196
    const int NB_ZERO = (NNODE + 255) / 256;    // 782

    // (1) fused prep: weight fold/convert + zero_deg
    prep_all<<<352 + NB_ZERO, 256>>>(W_in_user, W_in_item, W1, W2, b_in_user, b_in_item);
    // (2) degree histogram
    build_deg<<<(E_TOT + 255) / 256, 256>>>(edge_ui, edge_iu);
    // (3) scan stage 1
    scan1<<<NB_SCAN, 1024>>>();
    // (4) proj GEMM user  (early so ncu -s captures it)
    gemm_mma<256, true, float><<<(N_USER + 127) / 128, 256, SMEM_GEMM>>>(
        x_user, wt_hi + WT_WU, wt_lo + WT_WU, bfold, hw16, N_USER);
    // (5) scan stage 2
    scan2k<<<1, 256>>>();
    // (6) scan stage 3 + dinv
    scan3<<<NB_SCAN, 1024>>>();
    // (7) fill CSR
    fill_csr<<<(E_TOT + 255) / 256, 256>>>(edge_ui, edge_iu);
    // (8) proj GEMM item
    gemm_mma<256, true, float><<<(N_ITEM + 127) / 128, 256, SMEM_GEMM>>>(
        x_item, wt_hi + WT_WI, wt_lo + WT_WI, bfold + HID,
        hw16 + (size_t)N_USER * HID, N_ITEM);
    // (9) layer-1 aggregate -> h16 (fp16, relu)
    aggregate<__half><<<(NNODE * 32 + 255) / 256, 256>>>(hw16, h16, b1, 1);
    // (10) layer-2 GEMM
    gemm_mma<128, false, __half><<<(NNODE + 127) / 128, 256, SMEM_GEMM>>>(
        h16, wt_hi + WT_W2, wt_lo + WT_W2, nullptr, hw16, NNODE);
    // (11) layer-2 aggregate -> out (fp32)
    aggregate<float><<<(NNODE * 32 + 255) / 256, 256>>>(hw16, out, b2, 0);
}

// round 11
// speedup vs baseline: 3.2724x; 1.0786x over previous
#include <cuda_runtime.h>
#include <cuda_fp16.h>
#include <math.h>
#include <stdint.h>
#include <string.h>

#define N_USER 100000
#define N_ITEM 100000
#define NNODE  200000
#define E_HALF 600000
#define E_TOT  1200000
#define HID 128

// ------------------------- scratch (device globals, no alloc) ----------------
__device__ __half g_hw16[(size_t)NNODE * HID];   // pre-aggregation features
__device__ __half g_h16[(size_t)NNODE * HID];    // layer-1 activations (fp16)
__device__ float  g_dinv[NNODE];
__device__ int    g_deg[NNODE];
__device__ int    g_rowptr[NNODE + 1];
__device__ int    g_cursor[NNODE];
__device__ int    g_col[E_TOT];
__device__ int    g_bsums[256];
__device__ float  g_bfold[2][HID];               // b_in @ W1 per node type

// fp16 hi/lo planes of weights, transposed Wt[n][k]
#define WT_WU 0
#define WT_WI 32768
#define WT_W2 65536
__device__ __half g_wt_hi[81920];
__device__ __half g_wt_lo[81920];

// ------------------------- helpers -------------------------------------------
__device__ __forceinline__ uint32_t smem_u32(const void* p) {
    uint32_t a;
    asm("{ .reg .u64 t; cvta.to.shared.u64 t, %1; cvt.u32.u64 %0, t; }" : "=r"(a) : "l"(p));
    return a;
}

__device__ __forceinline__ uint32_t h2_as_u32(__half2 h) {
    uint32_t u;
    memcpy(&u, &h, 4);
    return u;
}

__device__ __forceinline__ void ldsm_x4(uint32_t& r0, uint32_t& r1,
                                        uint32_t& r2, uint32_t& r3, uint32_t addr) {
    asm volatile("ldmatrix.sync.aligned.m8n8.x4.shared.b16 {%0,%1,%2,%3}, [%4];"
                 : "=r"(r0), "=r"(r1), "=r"(r2), "=r"(r3) : "r"(addr));
}

__device__ __forceinline__ void mma16816(float* c, const uint32_t* a, const uint32_t* b) {
    asm volatile("mma.sync.aligned.m16n8k16.row.col.f32.f16.f16.f32 "
                 "{%0,%1,%2,%3}, {%4,%5,%6,%7}, {%8,%9}, {%0,%1,%2,%3};"
                 : "+f"(c[0]), "+f"(c[1]), "+f"(c[2]), "+f"(c[3])
                 : "r"(a[0]), "r"(a[1]), "r"(a[2]), "r"(a[3]), "r"(b[0]), "r"(b[1]));
}

__device__ __forceinline__ void cp_async16(uint32_t saddr, const void* g) {
    asm volatile("cp.async.cg.shared.global [%0], [%1], 16;" :: "r"(saddr), "l"(g));
}
__device__ __forceinline__ void cp_commit() {
    asm volatile("cp.async.commit_group;" ::: "memory");
}
__device__ __forceinline__ void cp_wait0() {
    asm volatile("cp.async.wait_group 0;" ::: "memory");
}

// ------------------------- fused prep -----------------------------------------
__global__ void prep_all(const float* __restrict__ Wu, const float* __restrict__ Wi,
                         const float* __restrict__ W1, const float* __restrict__ W2,
                         const float* __restrict__ bu, const float* __restrict__ bi) {
    int blk = blockIdx.x, tid = threadIdx.x;
    if (blk < 256) {
        int i = blk * 256 + tid;
        int type = i >> 15;
        int k = (i >> 7) & 255;
        int n = i & 127;
        const float* Win = type ? Wi : Wu;
        float s = 0.f;
        #pragma unroll 8
        for (int j = 0; j < 128; j++)
            s = fmaf(Win[(size_t)k * 128 + j], W1[(size_t)j * 128 + n], s);
        __half hi = __float2half_rn(s);
        __half lo = __float2half_rn(s - __half2float(hi));
        int dst = (type ? WT_WI : WT_WU) + n * 256 + k;
        g_wt_hi[dst] = hi;
        g_wt_lo[dst] = lo;
    } else if (blk < 320) {
        int i = (blk - 256) * 256 + tid;
        int k = i >> 7, n = i & 127;
        float w = W2[(size_t)k * 128 + n];
        __half hi = __float2half_rn(w);
        __half lo = __float2half_rn(w - __half2float(hi));
        int dst = WT_W2 + n * 128 + k;
        g_wt_hi[dst] = hi;
        g_wt_lo[dst] = lo;
    } else if (blk < 352) {
        int w = (blk - 320) * 8 + (tid >> 5);
        int lane = tid & 31;
        int type = w >> 7, n = w & 127;
        const float* b = type ? bi : bu;
        float s = 0.f;
        #pragma unroll
        for (int q = 0; q < 4; q++) {
            int j = lane + q * 32;
            s = fmaf(b[j], W1[(size_t)j * 128 + n], s);
        }
        #pragma unroll
        for (int off = 16; off > 0; off >>= 1)
            s += __shfl_down_sync(0xffffffff, s, off);
        if (lane == 0) g_bfold[type][n] = s;
    } else {
        int i = (blk - 352) * 256 + tid;
        if (i < NNODE) g_deg[i] = 0;
    }
}

// ------------------------- CSR build ------------------------------------------
__global__ void build_deg(const int* __restrict__ eui, const int* __restrict__ eiu) {
    int i = blockIdx.x * blockDim.x + threadIdx.x;
    if (i < E_HALF) {
        atomicAdd(&g_deg[eui[E_HALF + i] + N_USER], 1);
    } else if (i < E_TOT) {
        atomicAdd(&g_deg[eiu[E_HALF + (i - E_HALF)]], 1);
    }
}

__global__ void scan1() {
    __shared__ int sm[1024];
    int tx = threadIdx.x;
    int i = blockIdx.x * 1024 + tx;
    int v = (i < NNODE) ? g_deg[i] : 0;
    sm[tx] = v;
    __syncthreads();
    #pragma unroll
    for (int off = 1; off < 1024; off <<= 1) {
        int t = (tx >= off) ? sm[tx - off] : 0;
        __syncthreads();
        sm[tx] += t;
        __syncthreads();
    }
    if (i < NNODE) g_rowptr[i] = sm[tx] - v;
    if (tx == 1023) g_bsums[blockIdx.x] = sm[1023];
}

__global__ void scan2k() {
    __shared__ int sm[256];
    int tx = threadIdx.x;
    int v = (tx < 196) ? g_bsums[tx] : 0;
    sm[tx] = v;
    __syncthreads();
    #pragma unroll
    for (int off = 1; off < 256; off <<= 1) {
        int t = (tx >= off) ? sm[tx - off] : 0;
        __syncthreads();
        sm[tx] += t;
        __syncthreads();
    }
    if (tx < 196) g_bsums[tx] = sm[tx] - v;
}

__global__ void scan3() {
    int tx = threadIdx.x;
    int i = blockIdx.x * 1024 + tx;
    if (i < NNODE) {
        int v = g_rowptr[i] + g_bsums[blockIdx.x];
        g_rowptr[i] = v;
        g_cursor[i] = v;
        g_dinv[i] = rsqrtf((float)(g_deg[i] + 1));
    }
    if (i == 0) g_rowptr[NNODE] = E_TOT;
}

__global__ void fill_csr(const int* __restrict__ eui, const int* __restrict__ eiu) {
    int i = blockIdx.x * blockDim.x + threadIdx.x;
    int s, d;
    if (i < E_HALF) {
        s = eui[i];
        d = eui[E_HALF + i] + N_USER;
    } else if (i < E_TOT) {
        int j = i - E_HALF;
        s = eiu[j] + N_USER;
        d = eiu[E_HALF + j];
    } else return;
    int pos = atomicAdd(&g_cursor[d], 1);
    g_col[pos] = s;
}

// ------------------------- HMMA GEMM ------------------------------------------
// C[M,128] = A[M,K] @ W[K,128]; A fp16 exact, W split hi/lo (2 products).
// K-step 32 between barriers; cp.async for fp16 A; DUAL merges user+item proj.
template <int K, bool BIAS, typename AT, bool DUAL>
__global__ __launch_bounds__(256, 2) void gemm_mma(
    const AT* __restrict__ A0, const AT* __restrict__ A1,
    const __half* __restrict__ Whi0, const __half* __restrict__ Whi1,
    const __half* __restrict__ Wlo0, const __half* __restrict__ Wlo1,
    const float* __restrict__ bias, __half* __restrict__ C, int M, int nbh)
{
    constexpr int WSTRIDE = 272;           // 128 halves + 8 pad
    constexpr int WBYTES  = 128 * WSTRIDE; // 34816/plane
    constexpr int ASTRIDE = 80;            // 32 halves + 8 pad
    constexpr int ABYTES  = 128 * ASTRIDE; // 10240
    constexpr int N32     = K / 32;

    extern __shared__ char smem[];
    char* sWhi = smem;
    char* sWlo = smem + WBYTES;
    char* sA   = smem + 2 * WBYTES;        // 2 double-buffered 32-K A tiles

    const int tid = threadIdx.x, lane = tid & 31, wid = tid >> 5;
    const int m0 = (wid >> 2) * 64, n0 = (wid & 3) * 32;

    const int bx = blockIdx.x;
    const int item = DUAL ? (bx >= nbh ? 1 : 0) : 0;
    const AT* __restrict__ A = item ? A1 : A0;
    const __half* __restrict__ Wt_hi = item ? Whi1 : Whi0;
    const __half* __restrict__ Wt_lo = item ? Wlo1 : Wlo0;
    const int block_row = ((DUAL && item) ? bx - nbh : bx) * 128;
    __half* __restrict__ Cc = C + (item ? (size_t)N_USER * HID : 0);
    const float* bs = bias + (DUAL ? item * HID : 0);

    const uint32_t sWhi_u = smem_u32(sWhi);
    const uint32_t sWlo_u = smem_u32(sWlo);
    const uint32_t sA_u   = smem_u32(sA);

    auto stage_w = [&](int kh) {
        const uint32_t* wh = (const uint32_t*)Wt_hi;
        const uint32_t* wl = (const uint32_t*)Wt_lo;
        #pragma unroll 4
        for (int i = tid; i < 128 * 64; i += 256) {
            int n = i >> 6, kp = i & 63;
            int src = n * (K / 2) + kh * 64 + kp;
            *(uint32_t*)(sWhi + n * WSTRIDE + kp * 4) = wh[src];
            *(uint32_t*)(sWlo + n * WSTRIDE + kp * 4) = wl[src];
        }
    };

    float acc[4][4][4];
    #pragma unroll
    for (int a = 0; a < 4; a++)
        #pragma unroll
        for (int b = 0; b < 4; b++)
            #pragma unroll
            for (int c = 0; c < 4; c++) acc[a][b][c] = 0.f;

    const uint32_t aoff = (uint32_t)((lane & 15) * ASTRIDE + ((lane & 16) ? 16 : 0));
    const uint32_t woff = (uint32_t)((((lane & 16) ? 8 : 0) + (lane & 7)) * WSTRIDE +
                                     ((lane & 8) ? 16 : 0));

    float4 vf[4];   // fp32 staging registers (proj path)

    auto load_tile = [&](int ck) {       // fp32 path: LDG into regs
        #pragma unroll
        for (int q = 0; q < 4; q++) {
            int j = tid + 256 * q;
            int r = j >> 3, p = j & 7;
            int gr = block_row + r;
            if (gr > M - 1) gr = M - 1;
            vf[q] = *(const float4*)((const float*)A + (size_t)gr * K + ck * 32 + p * 4);
        }
    };
    auto store_tile = [&](int db) {      // fp32 path: convert + STS
        char* buf = sA + db * ABYTES;
        #pragma unroll
        for (int q = 0; q < 4; q++) {
            int j = tid + 256 * q;
            int r = j >> 3, p = j & 7;
            uint2 o;
            o.x = h2_as_u32(__floats2half2_rn(vf[q].x, vf[q].y));
            o.y = h2_as_u32(__floats2half2_rn(vf[q].z, vf[q].w));
            *(uint2*)(buf + r * ASTRIDE + p * 8) = o;
        }
    };
    auto cp_tile = [&](int ck, int db) { // fp16 path: cp.async direct
        uint32_t base = sA_u + db * ABYTES;
        #pragma unroll
        for (int q = 0; q < 2; q++) {
            int j = tid + 256 * q;
            int r = j >> 2, p = j & 3;
            int gr = block_row + r;
            if (gr > M - 1) gr = M - 1;
            cp_async16(base + r * ASTRIDE + p * 16,
                       (const __half*)A + (size_t)gr * K + ck * 32 + p * 8);
        }
        cp_commit();
    };

    // prologue
    stage_w(0);
    if constexpr (sizeof(AT) == 2) {
        cp_tile(0, 0);
        cp_wait0();
    } else {
        load_tile(0);
        store_tile(0);
    }
    __syncthreads();

    for (int i = 0; i < N32; i++) {
        if (i + 1 < N32) {
            if constexpr (sizeof(AT) == 2) cp_tile(i + 1, (i + 1) & 1);
            else load_tile(i + 1);
        }

        const uint32_t abase = sA_u + (i & 1) * ABYTES;

        #pragma unroll
        for (int c2 = 0; c2 < 2; c2++) {
            const int kk = (i * 2 + c2) & 7;
            const uint32_t wk = (uint32_t)(n0 * WSTRIDE + kk * 32) + woff;

            uint32_t wh[4][2], wl[4][2], af[4][4];
            #pragma unroll
            for (int nt2 = 0; nt2 < 2; nt2++) {
                uint32_t q0, q1, q2, q3;
                ldsm_x4(q0, q1, q2, q3, sWhi_u + wk + nt2 * 16 * WSTRIDE);
                wh[nt2 * 2 + 0][0] = q0; wh[nt2 * 2 + 0][1] = q1;
                wh[nt2 * 2 + 1][0] = q2; wh[nt2 * 2 + 1][1] = q3;
                ldsm_x4(q0, q1, q2, q3, sWlo_u + wk + nt2 * 16 * WSTRIDE);
                wl[nt2 * 2 + 0][0] = q0; wl[nt2 * 2 + 0][1] = q1;
                wl[nt2 * 2 + 1][0] = q2; wl[nt2 * 2 + 1][1] = q3;
            }
            #pragma unroll
            for (int mt = 0; mt < 4; mt++)
                ldsm_x4(af[mt][0], af[mt][1], af[mt][2], af[mt][3],
                        abase + (uint32_t)((m0 + mt * 16) * ASTRIDE) + aoff + c2 * 32);

            #pragma unroll
            for (int mt = 0; mt < 4; mt++)
                #pragma unroll
                for (int nt = 0; nt < 4; nt++)
                    mma16816(acc[mt][nt], af[mt], wh[nt]);
            #pragma unroll
            for (int mt = 0; mt < 4; mt++)
                #pragma unroll
                for (int nt = 0; nt < 4; nt++)
                    mma16816(acc[mt][nt], af[mt], wl[nt]);
        }

        if (i + 1 < N32) {
            if constexpr (sizeof(AT) == 2) cp_wait0();
            else store_tile((i + 1) & 1);
        }
        __syncthreads();

        if constexpr (K > 128) {
            if (i == N32 / 2 - 1) {
                stage_w(1);
                __syncthreads();
            }
        }
    }

    // epilogue: fp16 out
    #pragma unroll
    for (int nt = 0; nt < 4; nt++) {
        int col = n0 + nt * 8 + 2 * (lane & 3);
        float b0 = 0.f, b1 = 0.f;
        if (BIAS) { b0 = bs[col]; b1 = bs[col + 1]; }
        #pragma unroll
        for (int mt = 0; mt < 4; mt++) {
            int row = block_row + m0 + mt * 16 + (lane >> 2);
            if (row < M)
                *(__half2*)(Cc + (size_t)row * 128 + col) =
                    __floats2half2_rn(acc[mt][nt][0] + b0, acc[mt][nt][1] + b1);
            if (row + 8 < M)
                *(__half2*)(Cc + (size_t)(row + 8) * 128 + col) =
                    __floats2half2_rn(acc[mt][nt][2] + b0, acc[mt][nt][3] + b1);
        }
    }
}

// ------------------------- aggregation: one warp per dst node ----------------
template <typename OUTT>
__global__ __launch_bounds__(256)
void aggregate(const __half* __restrict__ hw, OUTT* __restrict__ out,
               const float* __restrict__ bias, int relu) {
    int node = (blockIdx.x * blockDim.x + threadIdx.x) >> 5;
    int lane = threadIdx.x & 31;
    if (node >= NNODE) return;

    float dv = g_dinv[node];
    float ws = dv * dv;

    const __half2* self = (const __half2*)(hw + (size_t)node * HID) + lane * 2;
    float2 s0 = __half22float2(self[0]);
    float2 s1 = __half22float2(self[1]);
    float4 acc = make_float4(s0.x * ws, s0.y * ws, s1.x * ws, s1.y * ws);

    int e = g_rowptr[node];
    int end = g_rowptr[node + 1];
    for (; e + 1 < end; e += 2) {
        int c0 = g_col[e], c1 = g_col[e + 1];
        float w0 = g_dinv[c0] * dv;
        float w1 = g_dinv[c1] * dv;
        const __half2* u0 = (const __half2*)(hw + (size_t)c0 * HID) + lane * 2;
        const __half2* u1 = (const __half2*)(hw + (size_t)c1 * HID) + lane * 2;
        float2 a0 = __half22float2(u0[0]), a1 = __half22float2(u0[1]);
        float2 b0 = __half22float2(u1[0]), b1 = __half22float2(u1[1]);
        acc.x = fmaf(w0, a0.x, acc.x); acc.y = fmaf(w0, a0.y, acc.y);
        acc.z = fmaf(w0, a1.x, acc.z); acc.w = fmaf(w0, a1.y, acc.w);
        acc.x = fmaf(w1, b0.x, acc.x); acc.y = fmaf(w1, b0.y, acc.y);
        acc.z = fmaf(w1, b1.x, acc.z); acc.w = fmaf(w1, b1.y, acc.w);
    }
    if (e < end) {
        int c0 = g_col[e];
        float w0 = g_dinv[c0] * dv;
        const __half2* u0 = (const __half2*)(hw + (size_t)c0 * HID) + lane * 2;
        float2 a0 = __half22float2(u0[0]), a1 = __half22float2(u0[1]);
        acc.x = fmaf(w0, a0.x, acc.x); acc.y = fmaf(w0, a0.y, acc.y);
        acc.z = fmaf(w0, a1.x, acc.z); acc.w = fmaf(w0, a1.y, acc.w);
    }

    float4 b = ((const float4*)bias)[lane];
    acc.x += b.x; acc.y += b.y; acc.z += b.z; acc.w += b.w;
    if (relu) {
        acc.x = fmaxf(acc.x, 0.f); acc.y = fmaxf(acc.y, 0.f);
        acc.z = fmaxf(acc.z, 0.f); acc.w = fmaxf(acc.w, 0.f);
    }
    if constexpr (sizeof(OUTT) == 4) {
        ((float4*)((float*)out + (size_t)node * HID))[lane] = acc;
    } else {
        __half2* op = (__half2*)((__half*)out + (size_t)node * HID) + lane * 2;
        op[0] = __floats2half2_rn(acc.x, acc.y);
        op[1] = __floats2half2_rn(acc.z, acc.w);
    }
}

// ------------------------- driver --------------------------------------------
extern "C" void kernel_launch(void* const* d_in, const int* in_sizes, int n_in,
                              void* d_out, int out_size) {
    const float* x_user    = (const float*)d_in[0];
    const float* x_item    = (const float*)d_in[1];
    const int*   edge_ui   = (const int*)d_in[2];
    const int*   edge_iu   = (const int*)d_in[3];
    const float* W_in_user = (const float*)d_in[4];
    const float* b_in_user = (const float*)d_in[5];
    const float* W_in_item = (const float*)d_in[6];
    const float* b_in_item = (const float*)d_in[7];
    const float* W1        = (const float*)d_in[8];
    const float* b1        = (const float*)d_in[9];
    const float* W2        = (const float*)d_in[10];
    const float* b2        = (const float*)d_in[11];
    float* out = (float*)d_out;

    __half* hw16; __half* h16;
    __half* wt_hi; __half* wt_lo;
    float* bfold;
    cudaGetSymbolAddress((void**)&hw16,  g_hw16);
    cudaGetSymbolAddress((void**)&h16,   g_h16);
    cudaGetSymbolAddress((void**)&wt_hi, g_wt_hi);
    cudaGetSymbolAddress((void**)&wt_lo, g_wt_lo);
    cudaGetSymbolAddress((void**)&bfold, g_bfold);

    const int SMEM_GEMM = 2 * 34816 + 2 * 10240;   // 90112
    cudaFuncSetAttribute((const void*)gemm_mma<256, true, float, true>,
                         cudaFuncAttributeMaxDynamicSharedMemorySize, SMEM_GEMM);
    cudaFuncSetAttribute((const void*)gemm_mma<128, false, __half, false>,
                         cudaFuncAttributeMaxDynamicSharedMemorySize, SMEM_GEMM);

    const int NB_SCAN = (NNODE + 1023) / 1024;  // 196
    const int NB_ZERO = (NNODE + 255) / 256;    // 782
    const int NBU = (N_USER + 127) / 128;       // 782
    const int NB2 = (NNODE + 127) / 128;        // 1563

    // (1) fused prep
    prep_all<<<352 + NB_ZERO, 256>>>(W_in_user, W_in_item, W1, W2, b_in_user, b_in_item);
    // (2) degree histogram
    build_deg<<<(E_TOT + 255) / 256, 256>>>(edge_ui, edge_iu);
    // (3) scan stage 1
    scan1<<<NB_SCAN, 1024>>>();
    // (4) merged proj GEMM (user + item)
    gemm_mma<256, true, float, true><<<2 * NBU, 256, SMEM_GEMM>>>(
        x_user, x_item, wt_hi + WT_WU, wt_hi + WT_WI, wt_lo + WT_WU, wt_lo + WT_WI,
        bfold, hw16, N_USER, NBU);
    // (5) scan stage 2
    scan2k<<<1, 256>>>();
    // (6) scan stage 3 + dinv
    scan3<<<NB_SCAN, 1024>>>();
    // (7) fill CSR
    fill_csr<<<(E_TOT + 255) / 256, 256>>>(edge_ui, edge_iu);
    // (8) layer-1 aggregate -> h16 (fp16, relu)
    aggregate<__half><<<(NNODE * 32 + 255) / 256, 256>>>(hw16, h16, b1, 1);
    // (9) layer-2 GEMM (fp16 A via cp.async)
    gemm_mma<128, false, __half, false><<<NB2, 256, SMEM_GEMM>>>(
        h16, h16, wt_hi + WT_W2, wt_hi + WT_W2, wt_lo + WT_W2, wt_lo + WT_W2,
        b2, hw16, NNODE, NB2);
    // (10) layer-2 aggregate -> out (fp32)
    aggregate<float><<<(NNODE * 32 + 255) / 256, 256>>>(hw16, out, b2, 0);
}

// round 12
// speedup vs baseline: 3.5460x; 1.0836x over previous
#include <cuda_runtime.h>
#include <cuda_fp16.h>
#include <math.h>
#include <stdint.h>
#include <string.h>

#define N_USER 100000
#define N_ITEM 100000
#define NNODE  200000
#define E_HALF 600000
#define E_TOT  1200000
#define HID 128

// ------------------------- scratch (device globals, no alloc) ----------------
__device__ __half g_hw16[(size_t)NNODE * HID];   // pre-aggregation features
__device__ __half g_h16[(size_t)NNODE * HID];    // layer-1 activations (fp16)
__device__ float  g_dinv[NNODE];
__device__ int    g_deg[NNODE];
__device__ int    g_rowptr[NNODE + 1];
__device__ int    g_cursor[NNODE];
__device__ int    g_col[E_TOT];
__device__ int    g_bsums[256];
__device__ float  g_bfold[2][HID];               // b_in @ W1 per node type

// fp16 weights, transposed Wt[n][k]
#define WT_WU 0
#define WT_WI 32768
#define WT_W2 65536
__device__ __half g_wt[81920];

// ------------------------- helpers -------------------------------------------
__device__ __forceinline__ uint32_t smem_u32(const void* p) {
    uint32_t a;
    asm("{ .reg .u64 t; cvta.to.shared.u64 t, %1; cvt.u32.u64 %0, t; }" : "=r"(a) : "l"(p));
    return a;
}

__device__ __forceinline__ uint32_t h2_as_u32(__half2 h) {
    uint32_t u;
    memcpy(&u, &h, 4);
    return u;
}

__device__ __forceinline__ void ldsm_x4(uint32_t& r0, uint32_t& r1,
                                        uint32_t& r2, uint32_t& r3, uint32_t addr) {
    asm volatile("ldmatrix.sync.aligned.m8n8.x4.shared.b16 {%0,%1,%2,%3}, [%4];"
                 : "=r"(r0), "=r"(r1), "=r"(r2), "=r"(r3) : "r"(addr));
}

__device__ __forceinline__ void mma16816(float* c, const uint32_t* a, const uint32_t* b) {
    asm volatile("mma.sync.aligned.m16n8k16.row.col.f32.f16.f16.f32 "
                 "{%0,%1,%2,%3}, {%4,%5,%6,%7}, {%8,%9}, {%0,%1,%2,%3};"
                 : "+f"(c[0]), "+f"(c[1]), "+f"(c[2]), "+f"(c[3])
                 : "r"(a[0]), "r"(a[1]), "r"(a[2]), "r"(a[3]), "r"(b[0]), "r"(b[1]));
}

__device__ __forceinline__ void cp_async16(uint32_t saddr, const void* g) {
    asm volatile("cp.async.cg.shared.global [%0], [%1], 16;" :: "r"(saddr), "l"(g));
}
__device__ __forceinline__ void cp_commit() {
    asm volatile("cp.async.commit_group;" ::: "memory");
}
__device__ __forceinline__ void cp_wait0() {
    asm volatile("cp.async.wait_group 0;" ::: "memory");
}

// ------------------------- fused prep -----------------------------------------
__global__ void prep_all(const float* __restrict__ Wu, const float* __restrict__ Wi,
                         const float* __restrict__ W1, const float* __restrict__ W2,
                         const float* __restrict__ bu, const float* __restrict__ bi) {
    int blk = blockIdx.x, tid = threadIdx.x;
    if (blk < 256) {
        int i = blk * 256 + tid;
        int type = i >> 15;
        int k = (i >> 7) & 255;
        int n = i & 127;
        const float* Win = type ? Wi : Wu;
        float s = 0.f;
        #pragma unroll 8
        for (int j = 0; j < 128; j++)
            s = fmaf(Win[(size_t)k * 128 + j], W1[(size_t)j * 128 + n], s);
        g_wt[(type ? WT_WI : WT_WU) + n * 256 + k] = __float2half_rn(s);
    } else if (blk < 320) {
        int i = (blk - 256) * 256 + tid;
        int k = i >> 7, n = i & 127;
        g_wt[WT_W2 + n * 128 + k] = __float2half_rn(W2[(size_t)k * 128 + n]);
    } else if (blk < 352) {
        int w = (blk - 320) * 8 + (tid >> 5);
        int lane = tid & 31;
        int type = w >> 7, n = w & 127;
        const float* b = type ? bi : bu;
        float s = 0.f;
        #pragma unroll
        for (int q = 0; q < 4; q++) {
            int j = lane + q * 32;
            s = fmaf(b[j], W1[(size_t)j * 128 + n], s);
        }
        #pragma unroll
        for (int off = 16; off > 0; off >>= 1)
            s += __shfl_down_sync(0xffffffff, s, off);
        if (lane == 0) g_bfold[type][n] = s;
    } else {
        int i = (blk - 352) * 256 + tid;
        if (i < NNODE) g_deg[i] = 0;
    }
}

// ------------------------- CSR build ------------------------------------------
__global__ void build_deg(const int* __restrict__ eui, const int* __restrict__ eiu) {
    int i = blockIdx.x * blockDim.x + threadIdx.x;
    if (i < E_HALF) {
        atomicAdd(&g_deg[eui[E_HALF + i] + N_USER], 1);
    } else if (i < E_TOT) {
        atomicAdd(&g_deg[eiu[E_HALF + (i - E_HALF)]], 1);
    }
}

__global__ void scan1() {
    __shared__ int sm[1024];
    int tx = threadIdx.x;
    int i = blockIdx.x * 1024 + tx;
    int v = (i < NNODE) ? g_deg[i] : 0;
    sm[tx] = v;
    __syncthreads();
    #pragma unroll
    for (int off = 1; off < 1024; off <<= 1) {
        int t = (tx >= off) ? sm[tx - off] : 0;
        __syncthreads();
        sm[tx] += t;
        __syncthreads();
    }
    if (i < NNODE) g_rowptr[i] = sm[tx] - v;
    if (tx == 1023) g_bsums[blockIdx.x] = sm[1023];
}

__global__ void scan2k() {
    __shared__ int sm[256];
    int tx = threadIdx.x;
    int v = (tx < 196) ? g_bsums[tx] : 0;
    sm[tx] = v;
    __syncthreads();
    #pragma unroll
    for (int off = 1; off < 256; off <<= 1) {
        int t = (tx >= off) ? sm[tx - off] : 0;
        __syncthreads();
        sm[tx] += t;
        __syncthreads();
    }
    if (tx < 196) g_bsums[tx] = sm[tx] - v;
}

__global__ void scan3() {
    int tx = threadIdx.x;
    int i = blockIdx.x * 1024 + tx;
    if (i < NNODE) {
        int v = g_rowptr[i] + g_bsums[blockIdx.x];
        g_rowptr[i] = v;
        g_cursor[i] = v;
        g_dinv[i] = rsqrtf((float)(g_deg[i] + 1));
    }
    if (i == 0) g_rowptr[NNODE] = E_TOT;
}

__global__ void fill_csr(const int* __restrict__ eui, const int* __restrict__ eiu) {
    int i = blockIdx.x * blockDim.x + threadIdx.x;
    int s, d;
    if (i < E_HALF) {
        s = eui[i];
        d = eui[E_HALF + i] + N_USER;
    } else if (i < E_TOT) {
        int j = i - E_HALF;
        s = eiu[j] + N_USER;
        d = eiu[E_HALF + j];
    } else return;
    int pos = atomicAdd(&g_cursor[d], 1);
    g_col[pos] = s;
}

// ------------------------- HMMA GEMM ------------------------------------------
// C[M,128] = A[M,K] @ W[K,128]; A fp16 exact, W plain fp16 (single product).
// K-step 32 between barriers; cp.async for fp16 A; DUAL merges user+item proj.
template <int K, bool BIAS, typename AT, bool DUAL>
__global__ __launch_bounds__(256, 2) void gemm_mma(
    const AT* __restrict__ A0, const AT* __restrict__ A1,
    const __half* __restrict__ W0, const __half* __restrict__ W1p,
    const float* __restrict__ bias, __half* __restrict__ C, int M, int nbh)
{
    constexpr int WSTRIDE = 272;           // 128 halves + 8 pad
    constexpr int WBYTES  = 128 * WSTRIDE; // 34816
    constexpr int ASTRIDE = 80;            // 32 halves + 8 pad
    constexpr int ABYTES  = 128 * ASTRIDE; // 10240
    constexpr int N32     = K / 32;

    extern __shared__ char smem[];
    char* sW = smem;
    char* sA = smem + WBYTES;              // 2 double-buffered 32-K A tiles

    const int tid = threadIdx.x, lane = tid & 31, wid = tid >> 5;
    const int m0 = (wid >> 2) * 64, n0 = (wid & 3) * 32;

    const int bx = blockIdx.x;
    const int item = DUAL ? (bx >= nbh ? 1 : 0) : 0;
    const AT* __restrict__ A = item ? A1 : A0;
    const __half* __restrict__ Wt = item ? W1p : W0;
    const int block_row = ((DUAL && item) ? bx - nbh : bx) * 128;
    __half* __restrict__ Cc = C + (item ? (size_t)N_USER * HID : 0);
    const float* bs = bias + (DUAL ? item * HID : 0);

    const uint32_t sW_u = smem_u32(sW);
    const uint32_t sA_u = smem_u32(sA);

    auto stage_w = [&](int kh) {
        const uint32_t* wp = (const uint32_t*)Wt;
        #pragma unroll 4
        for (int i = tid; i < 128 * 64; i += 256) {
            int n = i >> 6, kp = i & 63;
            *(uint32_t*)(sW + n * WSTRIDE + kp * 4) = wp[n * (K / 2) + kh * 64 + kp];
        }
    };

    float acc[4][4][4];
    #pragma unroll
    for (int a = 0; a < 4; a++)
        #pragma unroll
        for (int b = 0; b < 4; b++)
            #pragma unroll
            for (int c = 0; c < 4; c++) acc[a][b][c] = 0.f;

    const uint32_t aoff = (uint32_t)((lane & 15) * ASTRIDE + ((lane & 16) ? 16 : 0));
    const uint32_t woff = (uint32_t)((((lane & 16) ? 8 : 0) + (lane & 7)) * WSTRIDE +
                                     ((lane & 8) ? 16 : 0));

    float4 vf[4];   // fp32 staging registers (proj path)

    auto load_tile = [&](int ck) {       // fp32 path: LDG into regs
        #pragma unroll
        for (int q = 0; q < 4; q++) {
            int j = tid + 256 * q;
            int r = j >> 3, p = j & 7;
            int gr = block_row + r;
            if (gr > M - 1) gr = M - 1;
            vf[q] = *(const float4*)((const float*)A + (size_t)gr * K + ck * 32 + p * 4);
        }
    };
    auto store_tile = [&](int db) {      // fp32 path: convert + STS
        char* buf = sA + db * ABYTES;
        #pragma unroll
        for (int q = 0; q < 4; q++) {
            int j = tid + 256 * q;
            int r = j >> 3, p = j & 7;
            uint2 o;
            o.x = h2_as_u32(__floats2half2_rn(vf[q].x, vf[q].y));
            o.y = h2_as_u32(__floats2half2_rn(vf[q].z, vf[q].w));
            *(uint2*)(buf + r * ASTRIDE + p * 8) = o;
        }
    };
    auto cp_tile = [&](int ck, int db) { // fp16 path: cp.async direct
        uint32_t base = sA_u + db * ABYTES;
        #pragma unroll
        for (int q = 0; q < 2; q++) {
            int j = tid + 256 * q;
            int r = j >> 2, p = j & 3;
            int gr = block_row + r;
            if (gr > M - 1) gr = M - 1;
            cp_async16(base + r * ASTRIDE + p * 16,
                       (const __half*)A + (size_t)gr * K + ck * 32 + p * 8);
        }
        cp_commit();
    };

    // prologue
    stage_w(0);
    if constexpr (sizeof(AT) == 2) {
        cp_tile(0, 0);
        cp_wait0();
    } else {
        load_tile(0);
        store_tile(0);
    }
    __syncthreads();

    for (int i = 0; i < N32; i++) {
        if (i + 1 < N32) {
            if constexpr (sizeof(AT) == 2) cp_tile(i + 1, (i + 1) & 1);
            else load_tile(i + 1);
        }

        const uint32_t abase = sA_u + (i & 1) * ABYTES;

        #pragma unroll
        for (int c2 = 0; c2 < 2; c2++) {
            const int kk = (i * 2 + c2) & 7;
            const uint32_t wk = (uint32_t)(n0 * WSTRIDE + kk * 32) + woff;

            uint32_t wh[4][2], af[4][4];
            #pragma unroll
            for (int nt2 = 0; nt2 < 2; nt2++) {
                uint32_t q0, q1, q2, q3;
                ldsm_x4(q0, q1, q2, q3, sW_u + wk + nt2 * 16 * WSTRIDE);
                wh[nt2 * 2 + 0][0] = q0; wh[nt2 * 2 + 0][1] = q1;
                wh[nt2 * 2 + 1][0] = q2; wh[nt2 * 2 + 1][1] = q3;
            }
            #pragma unroll
            for (int mt = 0; mt < 4; mt++)
                ldsm_x4(af[mt][0], af[mt][1], af[mt][2], af[mt][3],
                        abase + (uint32_t)((m0 + mt * 16) * ASTRIDE) + aoff + c2 * 32);

            #pragma unroll
            for (int mt = 0; mt < 4; mt++)
                #pragma unroll
                for (int nt = 0; nt < 4; nt++)
                    mma16816(acc[mt][nt], af[mt], wh[nt]);
        }

        if (i + 1 < N32) {
            if constexpr (sizeof(AT) == 2) cp_wait0();
            else store_tile((i + 1) & 1);
        }
        __syncthreads();

        if constexpr (K > 128) {
            if (i == N32 / 2 - 1) {
                stage_w(1);
                __syncthreads();
            }
        }
    }

    // epilogue: fp16 out
    #pragma unroll
    for (int nt = 0; nt < 4; nt++) {
        int col = n0 + nt * 8 + 2 * (lane & 3);
        float b0 = 0.f, b1 = 0.f;
        if (BIAS) { b0 = bs[col]; b1 = bs[col + 1]; }
        #pragma unroll
        for (int mt = 0; mt < 4; mt++) {
            int row = block_row + m0 + mt * 16 + (lane >> 2);
            if (row < M)
                *(__half2*)(Cc + (size_t)row * 128 + col) =
                    __floats2half2_rn(acc[mt][nt][0] + b0, acc[mt][nt][1] + b1);
            if (row + 8 < M)
                *(__half2*)(Cc + (size_t)(row + 8) * 128 + col) =
                    __floats2half2_rn(acc[mt][nt][2] + b0, acc[mt][nt][3] + b1);
        }
    }
}

// ------------------------- aggregation: one warp per dst node ----------------
template <typename OUTT>
__global__ __launch_bounds__(256)
void aggregate(const __half* __restrict__ hw, OUTT* __restrict__ out,
               const float* __restrict__ bias, int relu) {
    int node = (blockIdx.x * blockDim.x + threadIdx.x) >> 5;
    int lane = threadIdx.x & 31;
    if (node >= NNODE) return;

    float dv = g_dinv[node];
    float ws = dv * dv;

    const __half2* self = (const __half2*)(hw + (size_t)node * HID) + lane * 2;
    float2 s0 = __half22float2(self[0]);
    float2 s1 = __half22float2(self[1]);
    float4 acc = make_float4(s0.x * ws, s0.y * ws, s1.x * ws, s1.y * ws);

    int e = g_rowptr[node];
    int end = g_rowptr[node + 1];
    for (; e + 1 < end; e += 2) {
        int c0 = g_col[e], c1 = g_col[e + 1];
        float w0 = g_dinv[c0] * dv;
        float w1 = g_dinv[c1] * dv;
        const __half2* u0 = (const __half2*)(hw + (size_t)c0 * HID) + lane * 2;
        const __half2* u1 = (const __half2*)(hw + (size_t)c1 * HID) + lane * 2;
        float2 a0 = __half22float2(u0[0]), a1 = __half22float2(u0[1]);
        float2 b0 = __half22float2(u1[0]), b1 = __half22float2(u1[1]);
        acc.x = fmaf(w0, a0.x, acc.x); acc.y = fmaf(w0, a0.y, acc.y);
        acc.z = fmaf(w0, a1.x, acc.z); acc.w = fmaf(w0, a1.y, acc.w);
        acc.x = fmaf(w1, b0.x, acc.x); acc.y = fmaf(w1, b0.y, acc.y);
        acc.z = fmaf(w1, b1.x, acc.z); acc.w = fmaf(w1, b1.y, acc.w);
    }
    if (e < end) {
        int c0 = g_col[e];
        float w0 = g_dinv[c0] * dv;
        const __half2* u0 = (const __half2*)(hw + (size_t)c0 * HID) + lane * 2;
        float2 a0 = __half22float2(u0[0]), a1 = __half22float2(u0[1]);
        acc.x = fmaf(w0, a0.x, acc.x); acc.y = fmaf(w0, a0.y, acc.y);
        acc.z = fmaf(w0, a1.x, acc.z); acc.w = fmaf(w0, a1.y, acc.w);
    }

    float4 b = ((const float4*)bias)[lane];
    acc.x += b.x; acc.y += b.y; acc.z += b.z; acc.w += b.w;
    if (relu) {
        acc.x = fmaxf(acc.x, 0.f); acc.y = fmaxf(acc.y, 0.f);
        acc.z = fmaxf(acc.z, 0.f); acc.w = fmaxf(acc.w, 0.f);
    }
    if constexpr (sizeof(OUTT) == 4) {
        ((float4*)((float*)out + (size_t)node * HID))[lane] = acc;
    } else {
        __half2* op = (__half2*)((__half*)out + (size_t)node * HID) + lane * 2;
        op[0] = __floats2half2_rn(acc.x, acc.y);
        op[1] = __floats2half2_rn(acc.z, acc.w);
    }
}

// ------------------------- driver --------------------------------------------
extern "C" void kernel_launch(void* const* d_in, const int* in_sizes, int n_in,
                              void* d_out, int out_size) {
    const float* x_user    = (const float*)d_in[0];
    const float* x_item    = (const float*)d_in[1];
    const int*   edge_ui   = (const int*)d_in[2];
    const int*   edge_iu   = (const int*)d_in[3];
    const float* W_in_user = (const float*)d_in[4];
    const float* b_in_user = (const float*)d_in[5];
    const float* W_in_item = (const float*)d_in[6];
    const float* b_in_item = (const float*)d_in[7];
    const float* W1        = (const float*)d_in[8];
    const float* b1        = (const float*)d_in[9];
    const float* W2        = (const float*)d_in[10];
    const float* b2        = (const float*)d_in[11];
    float* out = (float*)d_out;

    __half* hw16; __half* h16;
    __half* wt;
    float* bfold;
    cudaGetSymbolAddress((void**)&hw16,  g_hw16);
    cudaGetSymbolAddress((void**)&h16,   g_h16);
    cudaGetSymbolAddress((void**)&wt,    g_wt);
    cudaGetSymbolAddress((void**)&bfold, g_bfold);

    const int SMEM_GEMM = 34816 + 2 * 10240;   // 55296
    cudaFuncSetAttribute((const void*)gemm_mma<256, true, float, true>,
                         cudaFuncAttributeMaxDynamicSharedMemorySize, SMEM_GEMM);
    cudaFuncSetAttribute((const void*)gemm_mma<128, false, __half, false>,
                         cudaFuncAttributeMaxDynamicSharedMemorySize, SMEM_GEMM);

    const int NB_SCAN = (NNODE + 1023) / 1024;  // 196
    const int NB_ZERO = (NNODE + 255) / 256;    // 782
    const int NBU = (N_USER + 127) / 128;       // 782
    const int NB2 = (NNODE + 127) / 128;        // 1563

    // (1) fused prep
    prep_all<<<352 + NB_ZERO, 256>>>(W_in_user, W_in_item, W1, W2, b_in_user, b_in_item);
    // (2) degree histogram
    build_deg<<<(E_TOT + 255) / 256, 256>>>(edge_ui, edge_iu);
    // (3) scan stage 1
    scan1<<<NB_SCAN, 1024>>>();
    // (4) merged proj GEMM (user + item)
    gemm_mma<256, true, float, true><<<2 * NBU, 256, SMEM_GEMM>>>(
        x_user, x_item, wt + WT_WU, wt + WT_WI, bfold, hw16, N_USER, NBU);
    // (5) scan stage 2
    scan2k<<<1, 256>>>();
    // (6) scan stage 3 + dinv
    scan3<<<NB_SCAN, 1024>>>();
    // (7) fill CSR
    fill_csr<<<(E_TOT + 255) / 256, 256>>>(edge_ui, edge_iu);
    // (8) layer-1 aggregate -> h16 (fp16, relu)
    aggregate<__half><<<(NNODE * 32 + 255) / 256, 256>>>(hw16, h16, b1, 1);
    // (9) layer-2 GEMM (fp16 A via cp.async)
    gemm_mma<128, false, __half, false><<<NB2, 256, SMEM_GEMM>>>(
        h16, h16, wt + WT_W2, wt + WT_W2, b2, hw16, NNODE, NB2);
    // (10) layer-2 aggregate -> out (fp32)
    aggregate<float><<<(NNODE * 32 + 255) / 256, 256>>>(hw16, out, b2, 0);
}